// round 2
// baseline (speedup 1.0000x reference)
#include <cuda_runtime.h>
#include <math.h>

// ---------------- problem constants ----------------
#define NTOK   6272          // B*N = 32*196 tokens
#define DMODEL 768
#define FFDIM  3072
#define QKVDIM 2304
#define NHEAD  12
#define DHEAD  64
#define NSEQ   196
#define NLAYER 12

// ---------------- scratch (device globals; no allocation allowed) ----------------
__device__ float g_h  [NTOK * DMODEL];   // residual stream
__device__ float g_y  [NTOK * DMODEL];   // LN output
__device__ float g_qkv[NTOK * QKVDIM];
__device__ float g_o  [NTOK * DMODEL];   // attention output
__device__ float g_ff [NTOK * FFDIM];
__device__ float g_im [NTOK * DMODEL];   // im2col patches

// ---------------- im2col: (B,3,224,224) -> (6272, 768) with (c,i,j) inner order ----------------
__global__ void im2col_kernel(const float* __restrict__ x, float* __restrict__ out) {
    int idx = blockIdx.x * 256 + threadIdx.x;
    if (idx >= NTOK * DMODEL) return;
    int t = idx / 768, r = idx % 768;
    int c = r >> 8;               // /256
    int ij = r & 255;
    int i = ij >> 4, j = ij & 15;
    int b = t / 196, p = t % 196;
    int py = p / 14, px = p % 14;
    out[idx] = x[((size_t)(b * 3 + c) * 224 + py * 16 + i) * 224 + px * 16 + j];
}

// ---------------- GEMM: C[M,N] = A[M,K] @ W[N,K]^T + bias (+gelu) (+pos) (+res) ----------------
// 128x128 block tile, BK=16, 256 threads, 8x8 per thread.
// All M,N divisible by 128; all K divisible by 16 in this model -> no bounds checks.
__global__ void __launch_bounds__(256) gemm_kernel(
    const float* __restrict__ A, const float* __restrict__ W,
    const float* __restrict__ bias, const float* __restrict__ res,
    const float* __restrict__ pos, float* __restrict__ C,
    int M, int N, int K, int act)
{
    __shared__ float As[16][128];
    __shared__ float Ws[16][128];
    const int tid = threadIdx.x;
    const int bm = blockIdx.y * 128;
    const int bn = blockIdx.x * 128;
    const int tx = tid & 15;        // n dim
    const int ty = tid >> 4;        // m dim
    const int lrow = tid >> 2;      // 0..63 (loader row)
    const int lcol = (tid & 3) << 2;// 0,4,8,12 (loader k)

    float acc[8][8];
#pragma unroll
    for (int i = 0; i < 8; i++)
#pragma unroll
        for (int j = 0; j < 8; j++) acc[i][j] = 0.f;

    const float* Ap0 = A + (size_t)(bm + lrow)      * K + lcol;
    const float* Ap1 = A + (size_t)(bm + lrow + 64) * K + lcol;
    const float* Wp0 = W + (size_t)(bn + lrow)      * K + lcol;
    const float* Wp1 = W + (size_t)(bn + lrow + 64) * K + lcol;

    for (int k0 = 0; k0 < K; k0 += 16) {
        float4 a0 = *(const float4*)(Ap0 + k0);
        float4 a1 = *(const float4*)(Ap1 + k0);
        float4 w0 = *(const float4*)(Wp0 + k0);
        float4 w1 = *(const float4*)(Wp1 + k0);
        __syncthreads();   // previous iteration's reads done
        As[lcol + 0][lrow] = a0.x; As[lcol + 1][lrow] = a0.y;
        As[lcol + 2][lrow] = a0.z; As[lcol + 3][lrow] = a0.w;
        As[lcol + 0][lrow + 64] = a1.x; As[lcol + 1][lrow + 64] = a1.y;
        As[lcol + 2][lrow + 64] = a1.z; As[lcol + 3][lrow + 64] = a1.w;
        Ws[lcol + 0][lrow] = w0.x; Ws[lcol + 1][lrow] = w0.y;
        Ws[lcol + 2][lrow] = w0.z; Ws[lcol + 3][lrow] = w0.w;
        Ws[lcol + 0][lrow + 64] = w1.x; Ws[lcol + 1][lrow + 64] = w1.y;
        Ws[lcol + 2][lrow + 64] = w1.z; Ws[lcol + 3][lrow + 64] = w1.w;
        __syncthreads();
#pragma unroll
        for (int k = 0; k < 16; k++) {
            float ra[8], rb[8];
            *(float4*)&ra[0] = *(const float4*)&As[k][ty * 4];
            *(float4*)&ra[4] = *(const float4*)&As[k][64 + ty * 4];
            *(float4*)&rb[0] = *(const float4*)&Ws[k][tx * 4];
            *(float4*)&rb[4] = *(const float4*)&Ws[k][64 + tx * 4];
#pragma unroll
            for (int i = 0; i < 8; i++)
#pragma unroll
                for (int j = 0; j < 8; j++)
                    acc[i][j] += ra[i] * rb[j];
        }
    }

#pragma unroll
    for (int i = 0; i < 8; i++) {
        int m = bm + (i < 4 ? ty * 4 + i : 64 + ty * 4 + (i - 4));
        const float* resrow = res ? res + (size_t)m * N : nullptr;
        const float* posrow = pos ? pos + (size_t)(m % 196) * N : nullptr;
        float* crow = C + (size_t)m * N;
#pragma unroll
        for (int j = 0; j < 8; j++) {
            int n = bn + (j < 4 ? tx * 4 + j : 64 + tx * 4 + (j - 4));
            float v = acc[i][j] + bias[n];
            if (act) v = 0.5f * v * (1.f + erff(v * 0.70710678118654752f));
            if (posrow) v += posrow[n];
            if (resrow) v += resrow[n];
            crow[n] = v;
        }
    }
}

// ---------------- LayerNorm: per token, D=768, 256 threads/block ----------------
__global__ void __launch_bounds__(256) ln_kernel(
    const float* __restrict__ X, const float* __restrict__ w,
    const float* __restrict__ b, float* __restrict__ Y)
{
    const int t = blockIdx.x;
    const int tid = threadIdx.x;
    const float* xr = X + (size_t)t * DMODEL;
    float v0 = xr[tid], v1 = xr[tid + 256], v2 = xr[tid + 512];
    float s  = v0 + v1 + v2;
    float s2 = v0 * v0 + v1 * v1 + v2 * v2;
#pragma unroll
    for (int o = 16; o > 0; o >>= 1) {
        s  += __shfl_xor_sync(0xffffffffu, s,  o);
        s2 += __shfl_xor_sync(0xffffffffu, s2, o);
    }
    __shared__ float rs[8], rs2[8];
    __shared__ float mS, rS;
    int wid = tid >> 5, lane = tid & 31;
    if (lane == 0) { rs[wid] = s; rs2[wid] = s2; }
    __syncthreads();
    if (tid == 0) {
        float S = 0.f, S2 = 0.f;
        for (int k = 0; k < 8; k++) { S += rs[k]; S2 += rs2[k]; }
        float m = S * (1.f / 768.f);
        float var = S2 * (1.f / 768.f) - m * m;
        mS = m;
        rS = rsqrtf(var + 1e-5f);
    }
    __syncthreads();
    float m = mS, r = rS;
    float* yr = Y + (size_t)t * DMODEL;
    yr[tid]       = (v0 - m) * r * w[tid]       + b[tid];
    yr[tid + 256] = (v1 - m) * r * w[tid + 256] + b[tid + 256];
    yr[tid + 512] = (v2 - m) * r * w[tid + 512] + b[tid + 512];
}

// ---------------- Fused attention: one CTA per (b,h); K/V/Q/S resident in SMEM ----------------
#define NP 208   // keys padded to 13*16
#define ATTN_SMEM_FLOATS (64 * NP + NP * 64 + 64 * 64 + 64 * NP)
#define ATTN_SMEM_BYTES  (ATTN_SMEM_FLOATS * 4)

__global__ void __launch_bounds__(256) attn_kernel(
    const float* __restrict__ qkv, float* __restrict__ O)
{
    extern __shared__ float sm[];
    float* Kt = sm;                    // [64][NP]   K transposed (d-major), pad cols zero
    float* Vs = Kt + 64 * NP;          // [NP][64]   V, pad rows zero
    float* Qt = Vs + NP * 64;          // [64][64]   Q tile transposed (d-major), pre-scaled
    float* Ss = Qt + 64 * 64;          // [64][NP]   scores / probs

    const int tid = threadIdx.x;
    const int b = blockIdx.x / NHEAD;
    const int h = blockIdx.x % NHEAD;
    const float scale = 0.125f;        // 1/sqrt(64)
    const size_t base = (size_t)b * NSEQ * QKVDIM + h * DHEAD;

    // load K,V (zero padding rows/cols)
    for (int idx = tid; idx < NP * 64; idx += 256) {
        int m = idx >> 6, d = idx & 63;
        float kv = 0.f, vv = 0.f;
        if (m < NSEQ) {
            kv = qkv[base + (size_t)m * QKVDIM + 768  + d];
            vv = qkv[base + (size_t)m * QKVDIM + 1536 + d];
        }
        Kt[d * NP + m] = kv;
        Vs[m * 64 + d] = vv;
    }
    __syncthreads();

    const int tx = tid & 15, ty = tid >> 4;
    const int wid = tid >> 5, lane = tid & 31;

    for (int q0 = 0; q0 < NSEQ; q0 += 64) {
        // load Q tile transposed, pre-scaled (clamp padded rows; their output is never written)
        for (int idx = tid; idx < 64 * 64; idx += 256) {
            int i = idx >> 6, d = idx & 63;
            int r = q0 + i; if (r > NSEQ - 1) r = NSEQ - 1;
            Qt[d * 64 + i] = qkv[base + (size_t)r * QKVDIM + d] * scale;
        }
        __syncthreads();

        // S[64][208] = Q @ K^T ; thread tile 4(rows) x 13(strided cols)
        float acc[4][13];
#pragma unroll
        for (int i = 0; i < 4; i++)
#pragma unroll
            for (int j = 0; j < 13; j++) acc[i][j] = 0.f;
        for (int d = 0; d < 64; d++) {
            float ra[4];
            *(float4*)ra = *(const float4*)&Qt[d * 64 + ty * 4];
            float rb[13];
#pragma unroll
            for (int j = 0; j < 13; j++) rb[j] = Kt[d * NP + tx + j * 16];
#pragma unroll
            for (int i = 0; i < 4; i++)
#pragma unroll
                for (int j = 0; j < 13; j++) acc[i][j] += ra[i] * rb[j];
        }
#pragma unroll
        for (int i = 0; i < 4; i++)
#pragma unroll
            for (int j = 0; j < 13; j++)
                Ss[(ty * 4 + i) * NP + tx + j * 16] = acc[i][j];
        __syncthreads();

        // softmax over the 196 real keys; zero the 12 pad columns
        for (int row = wid; row < 64; row += 8) {
            float* srow = Ss + row * NP;
            float mx = -1e30f;
            for (int m = lane; m < NSEQ; m += 32) mx = fmaxf(mx, srow[m]);
#pragma unroll
            for (int o = 16; o > 0; o >>= 1) mx = fmaxf(mx, __shfl_xor_sync(0xffffffffu, mx, o));
            float sum = 0.f;
            for (int m = lane; m < NSEQ; m += 32) {
                float e = expf(srow[m] - mx);
                srow[m] = e;
                sum += e;
            }
#pragma unroll
            for (int o = 16; o > 0; o >>= 1) sum += __shfl_xor_sync(0xffffffffu, sum, o);
            float inv = 1.f / sum;
            for (int m = lane; m < NSEQ; m += 32) srow[m] *= inv;
            if (lane < NP - NSEQ) srow[NSEQ + lane] = 0.f;
        }
        __syncthreads();

        // O tile [64][64] = P @ V ; thread tile 4x4 (strided cols)
        float acc2[4][4];
#pragma unroll
        for (int i = 0; i < 4; i++)
#pragma unroll
            for (int j = 0; j < 4; j++) acc2[i][j] = 0.f;
        for (int m = 0; m < NP; m++) {
            float rb2[4];
#pragma unroll
            for (int j = 0; j < 4; j++) rb2[j] = Vs[m * 64 + tx + j * 16];
#pragma unroll
            for (int i = 0; i < 4; i++) {
                float pa = Ss[(ty * 4 + i) * NP + m];
#pragma unroll
                for (int j = 0; j < 4; j++) acc2[i][j] += pa * rb2[j];
            }
        }
#pragma unroll
        for (int i = 0; i < 4; i++) {
            int r = q0 + ty * 4 + i;
            if (r < NSEQ) {
#pragma unroll
                for (int j = 0; j < 4; j++)
                    O[(size_t)(b * NSEQ + r) * DMODEL + h * DHEAD + tx + j * 16] = acc2[i][j];
            }
        }
        __syncthreads();  // before Qt/Ss reuse in next tile
    }
}

// ---------------- launch ----------------
extern "C" void kernel_launch(void* const* d_in, const int* in_sizes, int n_in,
                              void* d_out, int out_size)
{
    const float* x       = (const float*)d_in[0];
    const float* patch_w = (const float*)d_in[1];
    const float* patch_b = (const float*)d_in[2];
    const float* pos     = (const float*)d_in[3];
    const float* ln1_w   = (const float*)d_in[4];
    const float* ln1_b   = (const float*)d_in[5];
    const float* qkv_w   = (const float*)d_in[6];
    const float* qkv_b   = (const float*)d_in[7];
    const float* proj_w  = (const float*)d_in[8];
    const float* proj_b  = (const float*)d_in[9];
    const float* ln2_w   = (const float*)d_in[10];
    const float* ln2_b   = (const float*)d_in[11];
    const float* fc1_w   = (const float*)d_in[12];
    const float* fc1_b   = (const float*)d_in[13];
    const float* fc2_w   = (const float*)d_in[14];
    const float* fc2_b   = (const float*)d_in[15];
    const float* lnf_w   = (const float*)d_in[16];
    const float* lnf_b   = (const float*)d_in[17];

    float *h, *y, *qkv, *o, *ff, *im;
    cudaGetSymbolAddress((void**)&h,   g_h);
    cudaGetSymbolAddress((void**)&y,   g_y);
    cudaGetSymbolAddress((void**)&qkv, g_qkv);
    cudaGetSymbolAddress((void**)&o,   g_o);
    cudaGetSymbolAddress((void**)&ff,  g_ff);
    cudaGetSymbolAddress((void**)&im,  g_im);

    cudaFuncSetAttribute(attn_kernel, cudaFuncAttributeMaxDynamicSharedMemorySize, ATTN_SMEM_BYTES);

    // patch embed: im2col + GEMM (bias + pos-embed fused in epilogue)
    im2col_kernel<<<(NTOK * DMODEL + 255) / 256, 256>>>(x, im);
    gemm_kernel<<<dim3(DMODEL / 128, NTOK / 128), 256>>>(
        im, patch_w, patch_b, nullptr, pos, h, NTOK, DMODEL, DMODEL, 0);

    for (int l = 0; l < NLAYER; l++) {
        ln_kernel<<<NTOK, 256>>>(h, ln1_w + l * DMODEL, ln1_b + l * DMODEL, y);
        gemm_kernel<<<dim3(QKVDIM / 128, NTOK / 128), 256>>>(
            y, qkv_w + (size_t)l * QKVDIM * DMODEL, qkv_b + l * QKVDIM,
            nullptr, nullptr, qkv, NTOK, QKVDIM, DMODEL, 0);
        attn_kernel<<<32 * NHEAD, 256, ATTN_SMEM_BYTES>>>(qkv, o);
        gemm_kernel<<<dim3(DMODEL / 128, NTOK / 128), 256>>>(
            o, proj_w + (size_t)l * DMODEL * DMODEL, proj_b + l * DMODEL,
            h, nullptr, h, NTOK, DMODEL, DMODEL, 0);
        ln_kernel<<<NTOK, 256>>>(h, ln2_w + l * DMODEL, ln2_b + l * DMODEL, y);
        gemm_kernel<<<dim3(FFDIM / 128, NTOK / 128), 256>>>(
            y, fc1_w + (size_t)l * FFDIM * DMODEL, fc1_b + l * FFDIM,
            nullptr, nullptr, ff, NTOK, FFDIM, DMODEL, 1);
        gemm_kernel<<<dim3(DMODEL / 128, NTOK / 128), 256>>>(
            ff, fc2_w + (size_t)l * DMODEL * FFDIM, fc2_b + l * DMODEL,
            h, nullptr, h, NTOK, DMODEL, FFDIM, 0);
    }
    ln_kernel<<<NTOK, 256>>>(h, lnf_w, lnf_b, (float*)d_out);
}

// round 4
// speedup vs baseline: 2.6377x; 2.6377x over previous
#include <cuda_runtime.h>
#include <math.h>

// ---------------- problem constants ----------------
#define NTOK   6272
#define DMODEL 768
#define FFDIM  3072
#define QKVDIM 2304
#define NHEAD  12
#define NSEQ   196
#define NLAYER 12

// ---------------- weight scratch offsets (floats) ----------------
#define OQKV   0
#define OPROJ  21233664
#define OFC1   28311552
#define OFC2   56623104
#define OPATCH 84934656
#define WTOTAL 85524480

__device__ __align__(256) float g_w  [WTOTAL];
__device__ __align__(256) float g_h  [NTOK * DMODEL];
__device__ __align__(256) float g_y  [NTOK * DMODEL];
__device__ __align__(256) float g_qkv[NTOK * QKVDIM];
__device__ __align__(256) float g_o  [NTOK * DMODEL];
__device__ __align__(256) float g_ff [NTOK * FFDIM];
__device__ __align__(256) float g_im [NTOK * DMODEL];

// ---------------- helpers ----------------
__device__ __forceinline__ unsigned smem_u32(const void* p) {
    unsigned a;
    asm("{ .reg .u64 t; cvta.to.shared.u64 t, %1; cvt.u32.u64 %0, t; }" : "=r"(a) : "l"(p));
    return a;
}
__device__ __forceinline__ float rna_tf32(float x) {
    unsigned u; asm("cvt.rna.tf32.f32 %0, %1;" : "=r"(u) : "f"(x));
    return __uint_as_float(u);
}
__device__ __forceinline__ void mma_tf32(float* c, const unsigned* a, const unsigned* b) {
    asm volatile("mma.sync.aligned.m16n8k8.row.col.f32.tf32.tf32.f32 "
        "{%0,%1,%2,%3}, {%4,%5,%6,%7}, {%8,%9}, {%0,%1,%2,%3};"
        : "+f"(c[0]), "+f"(c[1]), "+f"(c[2]), "+f"(c[3])
        : "r"(a[0]), "r"(a[1]), "r"(a[2]), "r"(a[3]), "r"(b[0]), "r"(b[1]));
}

// ---------------- weight tf32-rounding pass ----------------
__global__ void cvt_kernel(const float4* __restrict__ s, float4* __restrict__ d, int n4) {
    int i = blockIdx.x * 256 + threadIdx.x;
    if (i >= n4) return;
    float4 v = s[i];
    v.x = rna_tf32(v.x); v.y = rna_tf32(v.y); v.z = rna_tf32(v.z); v.w = rna_tf32(v.w);
    d[i] = v;
}

// ---------------- im2col (rounds to tf32) ----------------
__global__ void im2col_kernel(const float* __restrict__ x, float* __restrict__ out) {
    int idx = blockIdx.x * 256 + threadIdx.x;
    if (idx >= NTOK * DMODEL) return;
    int t = idx / 768, r = idx % 768;
    int c = r >> 8;
    int ij = r & 255;
    int i = ij >> 4, j = ij & 15;
    int b = t / 196, p = t % 196;
    int py = p / 14, px = p % 14;
    out[idx] = rna_tf32(x[((size_t)(b * 3 + c) * 224 + py * 16 + i) * 224 + px * 16 + j]);
}

// ---------------- tf32 mma.sync GEMM: C[M,N] = A[M,K] @ W[N,K]^T (+epilogue) ----------------
// 128x128x32 tile, 256 threads (8 warps 2x4), warp tile 64x32, 2-stage cp.async.
#define TPAD   36                      // 36 % 32 == 4 -> conflict-free frag loads
#define TILEF  (128 * TPAD)            // floats per tile
#define STAGEF (2 * TILEF)             // A + B per stage
#define GSMEM  (2 * STAGEF * 4)        // bytes, 2 stages = 73728

__device__ __forceinline__ void load_tile_pair(unsigned sdst, const float* __restrict__ Ab,
                                               const float* __restrict__ Wb, int K, int k0, int tid)
{
#pragma unroll
    for (int half = 0; half < 2; half++) {
        const float* src = (half ? Wb : Ab) + k0;
        unsigned base = sdst + half * (TILEF * 4);
#pragma unroll
        for (int j = 0; j < 4; j++) {
            int i = (j << 8) + tid;        // 0..1023 float4 slots
            int row = i >> 3, c4 = i & 7;
            unsigned d = base + (row * TPAD + (c4 << 2)) * 4;
            const float* s = src + (size_t)row * K + (c4 << 2);
            asm volatile("cp.async.cg.shared.global [%0], [%1], 16;" :: "r"(d), "l"(s));
        }
    }
}

__global__ void __launch_bounds__(256, 2) gemm_mma(
    const float* __restrict__ A, const float* __restrict__ W,
    const float* __restrict__ bias, const float* __restrict__ res,
    const float* __restrict__ pos, float* __restrict__ C,
    int N, int K, int act, int rnd)
{
    extern __shared__ float sm[];
    const int tid = threadIdx.x;
    const int bm = blockIdx.y << 7, bn = blockIdx.x << 7;
    const int wid = tid >> 5, lane = tid & 31;
    const int wm = wid >> 2, wn = wid & 3;       // 2 x 4 warps
    const int lr = lane >> 2, lc = lane & 3;
    const unsigned sbase = smem_u32(sm);

    const float* Ab = A + (size_t)bm * K;
    const float* Wb = W + (size_t)bn * K;
    const int NC = K >> 5;

    float acc[4][4][4];
#pragma unroll
    for (int mi = 0; mi < 4; mi++)
#pragma unroll
        for (int ni = 0; ni < 4; ni++)
#pragma unroll
            for (int q = 0; q < 4; q++) acc[mi][ni][q] = 0.f;

    load_tile_pair(sbase, Ab, Wb, K, 0, tid);
    asm volatile("cp.async.commit_group;" ::: "memory");

    for (int c = 0; c < NC; c++) {
        if (c + 1 < NC) {
            load_tile_pair(sbase + ((c + 1) & 1) * (STAGEF * 4), Ab, Wb, K, (c + 1) << 5, tid);
            asm volatile("cp.async.commit_group;" ::: "memory");
            asm volatile("cp.async.wait_group 1;" ::: "memory");
        } else {
            asm volatile("cp.async.wait_group 0;" ::: "memory");
        }
        __syncthreads();

        const float* As = sm + (c & 1) * STAGEF;
        const float* Bs = As + TILEF;
#pragma unroll
        for (int kk = 0; kk < 4; kk++) {
            const int kc = (kk << 3) + lc;
            unsigned af[4][4], bf[4][2];
#pragma unroll
            for (int mi = 0; mi < 4; mi++) {
                const float* ap = As + (wm * 64 + mi * 16 + lr) * TPAD + kc;
                af[mi][0] = __float_as_uint(ap[0]);
                af[mi][1] = __float_as_uint(ap[8 * TPAD]);
                af[mi][2] = __float_as_uint(ap[4]);
                af[mi][3] = __float_as_uint(ap[8 * TPAD + 4]);
            }
#pragma unroll
            for (int ni = 0; ni < 4; ni++) {
                const float* bp = Bs + (wn * 32 + ni * 8 + lr) * TPAD + kc;
                bf[ni][0] = __float_as_uint(bp[0]);
                bf[ni][1] = __float_as_uint(bp[4]);
            }
#pragma unroll
            for (int mi = 0; mi < 4; mi++)
#pragma unroll
                for (int ni = 0; ni < 4; ni++)
                    mma_tf32(acc[mi][ni], af[mi], bf[ni]);
        }
        __syncthreads();
    }

    // ---- epilogue ----
#pragma unroll
    for (int mi = 0; mi < 4; mi++) {
#pragma unroll
        for (int half = 0; half < 2; half++) {
            const int m = bm + wm * 64 + mi * 16 + lr + half * 8;
            float* crow = C + (size_t)m * N;
            const float* rrow = res ? res + (size_t)m * N : nullptr;
            const float* prow = pos ? pos + (size_t)(m % NSEQ) * N : nullptr;
#pragma unroll
            for (int ni = 0; ni < 4; ni++) {
                const int n = bn + wn * 32 + ni * 8 + 2 * lc;
                float v0 = acc[mi][ni][half * 2 + 0];
                float v1 = acc[mi][ni][half * 2 + 1];
                v0 += bias[n]; v1 += bias[n + 1];
                if (act) {
                    v0 = 0.5f * v0 * (1.f + erff(v0 * 0.70710678118654752f));
                    v1 = 0.5f * v1 * (1.f + erff(v1 * 0.70710678118654752f));
                }
                if (prow) { v0 += prow[n]; v1 += prow[n + 1]; }
                if (rrow) { v0 += rrow[n]; v1 += rrow[n + 1]; }
                if (rnd) { v0 = rna_tf32(v0); v1 = rna_tf32(v1); }
                *(float2*)(crow + n) = make_float2(v0, v1);
            }
        }
    }
}

// ---------------- LayerNorm ----------------
__global__ void __launch_bounds__(256) ln_kernel(
    const float* __restrict__ X, const float* __restrict__ w,
    const float* __restrict__ b, float* __restrict__ Y, int rnd)
{
    const int t = blockIdx.x;
    const int tid = threadIdx.x;
    const float* xr = X + (size_t)t * DMODEL;
    float v0 = xr[tid], v1 = xr[tid + 256], v2 = xr[tid + 512];
    float s = v0 + v1 + v2;
    float s2 = v0 * v0 + v1 * v1 + v2 * v2;
#pragma unroll
    for (int o = 16; o > 0; o >>= 1) {
        s += __shfl_xor_sync(0xffffffffu, s, o);
        s2 += __shfl_xor_sync(0xffffffffu, s2, o);
    }
    __shared__ float rs[8], rs2[8];
    __shared__ float mS, rS;
    int wid = tid >> 5, lane = tid & 31;
    if (lane == 0) { rs[wid] = s; rs2[wid] = s2; }
    __syncthreads();
    if (tid == 0) {
        float S = 0.f, S2 = 0.f;
        for (int k = 0; k < 8; k++) { S += rs[k]; S2 += rs2[k]; }
        float m = S * (1.f / 768.f);
        float var = S2 * (1.f / 768.f) - m * m;
        mS = m;
        rS = rsqrtf(var + 1e-5f);
    }
    __syncthreads();
    float m = mS, r = rS;
    float* yr = Y + (size_t)t * DMODEL;
    float o0 = (v0 - m) * r * w[tid] + b[tid];
    float o1 = (v1 - m) * r * w[tid + 256] + b[tid + 256];
    float o2 = (v2 - m) * r * w[tid + 512] + b[tid + 512];
    if (rnd) { o0 = rna_tf32(o0); o1 = rna_tf32(o1); o2 = rna_tf32(o2); }
    yr[tid] = o0; yr[tid + 256] = o1; yr[tid + 512] = o2;
}

// ---------------- fused attention (fp32 SIMT; output rounded to tf32) ----------------
#define NP 208
#define ATTN_SMEM_FLOATS (64 * NP + NP * 64 + 64 * 64 + 64 * NP)
#define ATTN_SMEM_BYTES  (ATTN_SMEM_FLOATS * 4)

__global__ void __launch_bounds__(256) attn_kernel(
    const float* __restrict__ qkv, float* __restrict__ O)
{
    extern __shared__ float sm[];
    float* Kt = sm;
    float* Vs = Kt + 64 * NP;
    float* Qt = Vs + NP * 64;
    float* Ss = Qt + 64 * 64;

    const int tid = threadIdx.x;
    const int b = blockIdx.x / NHEAD;
    const int h = blockIdx.x % NHEAD;
    const float scale = 0.125f;
    const size_t base = (size_t)b * NSEQ * QKVDIM + h * 64;

    for (int idx = tid; idx < NP * 64; idx += 256) {
        int m = idx >> 6, d = idx & 63;
        float kv = 0.f, vv = 0.f;
        if (m < NSEQ) {
            kv = qkv[base + (size_t)m * QKVDIM + 768 + d];
            vv = qkv[base + (size_t)m * QKVDIM + 1536 + d];
        }
        Kt[d * NP + m] = kv;
        Vs[m * 64 + d] = vv;
    }
    __syncthreads();

    const int tx = tid & 15, ty = tid >> 4;
    const int wid = tid >> 5, lane = tid & 31;

    for (int q0 = 0; q0 < NSEQ; q0 += 64) {
        for (int idx = tid; idx < 64 * 64; idx += 256) {
            int i = idx >> 6, d = idx & 63;
            int r = q0 + i; if (r > NSEQ - 1) r = NSEQ - 1;
            Qt[d * 64 + i] = qkv[base + (size_t)r * QKVDIM + d] * scale;
        }
        __syncthreads();

        float acc[4][13];
#pragma unroll
        for (int i = 0; i < 4; i++)
#pragma unroll
            for (int j = 0; j < 13; j++) acc[i][j] = 0.f;
        for (int d = 0; d < 64; d++) {
            float ra[4];
            *(float4*)ra = *(const float4*)&Qt[d * 64 + ty * 4];
            float rb[13];
#pragma unroll
            for (int j = 0; j < 13; j++) rb[j] = Kt[d * NP + tx + j * 16];
#pragma unroll
            for (int i = 0; i < 4; i++)
#pragma unroll
                for (int j = 0; j < 13; j++) acc[i][j] += ra[i] * rb[j];
        }
#pragma unroll
        for (int i = 0; i < 4; i++)
#pragma unroll
            for (int j = 0; j < 13; j++)
                Ss[(ty * 4 + i) * NP + tx + j * 16] = acc[i][j];
        __syncthreads();

        for (int row = wid; row < 64; row += 8) {
            float* srow = Ss + row * NP;
            float mx = -1e30f;
            for (int m = lane; m < NSEQ; m += 32) mx = fmaxf(mx, srow[m]);
#pragma unroll
            for (int o = 16; o > 0; o >>= 1) mx = fmaxf(mx, __shfl_xor_sync(0xffffffffu, mx, o));
            float sum = 0.f;
            for (int m = lane; m < NSEQ; m += 32) {
                float e = expf(srow[m] - mx);
                srow[m] = e;
                sum += e;
            }
#pragma unroll
            for (int o = 16; o > 0; o >>= 1) sum += __shfl_xor_sync(0xffffffffu, sum, o);
            float inv = 1.f / sum;
            for (int m = lane; m < NSEQ; m += 32) srow[m] *= inv;
            if (lane < NP - NSEQ) srow[NSEQ + lane] = 0.f;
        }
        __syncthreads();

        float acc2[4][4];
#pragma unroll
        for (int i = 0; i < 4; i++)
#pragma unroll
            for (int j = 0; j < 4; j++) acc2[i][j] = 0.f;
        for (int m = 0; m < NP; m++) {
            float rb2[4];
#pragma unroll
            for (int j = 0; j < 4; j++) rb2[j] = Vs[m * 64 + tx + j * 16];
#pragma unroll
            for (int i = 0; i < 4; i++) {
                float pa = Ss[(ty * 4 + i) * NP + m];
#pragma unroll
                for (int j = 0; j < 4; j++) acc2[i][j] += pa * rb2[j];
            }
        }
#pragma unroll
        for (int i = 0; i < 4; i++) {
            int r = q0 + ty * 4 + i;
            if (r < NSEQ) {
#pragma unroll
                for (int j = 0; j < 4; j++)
                    O[(size_t)(b * NSEQ + r) * DMODEL + h * 64 + tx + j * 16] = rna_tf32(acc2[i][j]);
            }
        }
        __syncthreads();
    }
}

// ---------------- launch ----------------
extern "C" void kernel_launch(void* const* d_in, const int* in_sizes, int n_in,
                              void* d_out, int out_size)
{
    const float* x       = (const float*)d_in[0];
    const float* patch_w = (const float*)d_in[1];
    const float* patch_b = (const float*)d_in[2];
    const float* pos     = (const float*)d_in[3];
    const float* ln1_w   = (const float*)d_in[4];
    const float* ln1_b   = (const float*)d_in[5];
    const float* qkv_w   = (const float*)d_in[6];
    const float* qkv_b   = (const float*)d_in[7];
    const float* proj_w  = (const float*)d_in[8];
    const float* proj_b  = (const float*)d_in[9];
    const float* ln2_w   = (const float*)d_in[10];
    const float* ln2_b   = (const float*)d_in[11];
    const float* fc1_w   = (const float*)d_in[12];
    const float* fc1_b   = (const float*)d_in[13];
    const float* fc2_w   = (const float*)d_in[14];
    const float* fc2_b   = (const float*)d_in[15];
    const float* lnf_w   = (const float*)d_in[16];
    const float* lnf_b   = (const float*)d_in[17];

    float *h, *y, *qkv, *o, *ff, *im, *w;
    cudaGetSymbolAddress((void**)&h,   g_h);
    cudaGetSymbolAddress((void**)&y,   g_y);
    cudaGetSymbolAddress((void**)&qkv, g_qkv);
    cudaGetSymbolAddress((void**)&o,   g_o);
    cudaGetSymbolAddress((void**)&ff,  g_ff);
    cudaGetSymbolAddress((void**)&im,  g_im);
    cudaGetSymbolAddress((void**)&w,   g_w);

    cudaFuncSetAttribute(attn_kernel, cudaFuncAttributeMaxDynamicSharedMemorySize, ATTN_SMEM_BYTES);
    cudaFuncSetAttribute(gemm_mma, cudaFuncAttributeMaxDynamicSharedMemorySize, GSMEM);

    // round weights to tf32 (rna) into scratch
    cvt_kernel<<<(21233664/4 + 255)/256, 256>>>((const float4*)qkv_w,  (float4*)(w + OQKV),   21233664/4);
    cvt_kernel<<<( 7077888/4 + 255)/256, 256>>>((const float4*)proj_w, (float4*)(w + OPROJ),   7077888/4);
    cvt_kernel<<<(28311552/4 + 255)/256, 256>>>((const float4*)fc1_w,  (float4*)(w + OFC1),   28311552/4);
    cvt_kernel<<<(28311552/4 + 255)/256, 256>>>((const float4*)fc2_w,  (float4*)(w + OFC2),   28311552/4);
    cvt_kernel<<<(  589824/4 + 255)/256, 256>>>((const float4*)patch_w,(float4*)(w + OPATCH),   589824/4);

    im2col_kernel<<<(NTOK * DMODEL + 255) / 256, 256>>>(x, im);
    gemm_mma<<<dim3(DMODEL / 128, NTOK / 128), 256, GSMEM>>>(
        im, w + OPATCH, patch_b, nullptr, pos, h, DMODEL, DMODEL, 0, 0);

    for (int l = 0; l < NLAYER; l++) {
        ln_kernel<<<NTOK, 256>>>(h, ln1_w + l * DMODEL, ln1_b + l * DMODEL, y, 1);
        gemm_mma<<<dim3(QKVDIM / 128, NTOK / 128), 256, GSMEM>>>(
            y, w + OQKV + (size_t)l * QKVDIM * DMODEL, qkv_b + l * QKVDIM,
            nullptr, nullptr, qkv, QKVDIM, DMODEL, 0, 0);
        attn_kernel<<<32 * NHEAD, 256, ATTN_SMEM_BYTES>>>(qkv, o);
        gemm_mma<<<dim3(DMODEL / 128, NTOK / 128), 256, GSMEM>>>(
            o, w + OPROJ + (size_t)l * DMODEL * DMODEL, proj_b + l * DMODEL,
            h, nullptr, h, DMODEL, DMODEL, 0, 0);
        ln_kernel<<<NTOK, 256>>>(h, ln2_w + l * DMODEL, ln2_b + l * DMODEL, y, 1);
        gemm_mma<<<dim3(FFDIM / 128, NTOK / 128), 256, GSMEM>>>(
            y, w + OFC1 + (size_t)l * FFDIM * DMODEL, fc1_b + l * FFDIM,
            nullptr, nullptr, ff, FFDIM, DMODEL, 1, 1);
        gemm_mma<<<dim3(DMODEL / 128, NTOK / 128), 256, GSMEM>>>(
            ff, w + OFC2 + (size_t)l * DMODEL * FFDIM, fc2_b + l * DMODEL,
            h, nullptr, h, DMODEL, FFDIM, 0, 0);
    }
    ln_kernel<<<NTOK, 256>>>(h, lnf_w, lnf_b, (float*)d_out, 0);
}

// round 5
// speedup vs baseline: 2.6552x; 1.0066x over previous
#include <cuda_runtime.h>
#include <math.h>

// ---------------- problem constants ----------------
#define NTOK   6272
#define DMODEL 768
#define FFDIM  3072
#define QKVDIM 2304
#define NHEAD  12
#define NSEQ   196
#define NLAYER 12

// ---------------- weight scratch offsets (floats) ----------------
#define OQKV   0
#define OPROJ  21233664
#define OFC1   28311552
#define OFC2   56623104
#define OPATCH 84934656
#define WTOTAL 85524480

__device__ __align__(256) float g_w  [WTOTAL];
__device__ __align__(256) float g_h  [NTOK * DMODEL];
__device__ __align__(256) float g_y  [NTOK * DMODEL];
__device__ __align__(256) float g_qkv[NTOK * QKVDIM];
__device__ __align__(256) float g_o  [NTOK * DMODEL];
__device__ __align__(256) float g_ff [NTOK * FFDIM];
__device__ __align__(256) float g_im [NTOK * DMODEL];

// ---------------- helpers ----------------
__device__ __forceinline__ float rna_tf32(float x) {
    unsigned u; asm("cvt.rna.tf32.f32 %0, %1;" : "=r"(u) : "f"(x));
    return __uint_as_float(u);
}
__device__ __forceinline__ void mma_tf32(float* c, const unsigned* a, const unsigned* b) {
    asm volatile("mma.sync.aligned.m16n8k8.row.col.f32.tf32.tf32.f32 "
        "{%0,%1,%2,%3}, {%4,%5,%6,%7}, {%8,%9}, {%0,%1,%2,%3};"
        : "+f"(c[0]), "+f"(c[1]), "+f"(c[2]), "+f"(c[3])
        : "r"(a[0]), "r"(a[1]), "r"(a[2]), "r"(a[3]), "r"(b[0]), "r"(b[1]));
}

// ---------------- weight tf32-rounding pass ----------------
__global__ void cvt_kernel(const float4* __restrict__ s, float4* __restrict__ d, int n4) {
    int i = blockIdx.x * 256 + threadIdx.x;
    if (i >= n4) return;
    float4 v = s[i];
    v.x = rna_tf32(v.x); v.y = rna_tf32(v.y); v.z = rna_tf32(v.z); v.w = rna_tf32(v.w);
    d[i] = v;
}

// ---------------- im2col (rounds to tf32) ----------------
__global__ void im2col_kernel(const float* __restrict__ x, float* __restrict__ out) {
    int idx = blockIdx.x * 256 + threadIdx.x;
    if (idx >= NTOK * DMODEL) return;
    int t = idx / 768, r = idx % 768;
    int c = r >> 8;
    int ij = r & 255;
    int i = ij >> 4, j = ij & 15;
    int b = t / 196, p = t % 196;
    int py = p / 14, px = p % 14;
    out[idx] = rna_tf32(x[((size_t)(b * 3 + c) * 224 + py * 16 + i) * 224 + px * 16 + j]);
}

// ---------------- tf32 mma.sync GEMM: C[M,N] = A[M,K] @ W[N,K]^T (+epilogue) ----------------
// 128x128x32 tile, 256 threads (8 warps 2x4), warp tile 64x32, 4-stage cp.async, 1 sync/chunk.
#define TPAD   36
#define TILEF  (128 * TPAD)
#define STAGEF (2 * TILEF)
#define GSMEM  (4 * STAGEF * 4)        // 147456 bytes

__device__ __forceinline__ void load_tile_pair(unsigned sdst, const float* __restrict__ Ab,
                                               const float* __restrict__ Wb, int K, int k0, int tid)
{
#pragma unroll
    for (int half = 0; half < 2; half++) {
        const float* src = (half ? Wb : Ab) + k0;
        unsigned base = sdst + half * (TILEF * 4);
#pragma unroll
        for (int j = 0; j < 4; j++) {
            int i = (j << 8) + tid;
            int row = i >> 3, c4 = i & 7;
            unsigned d = base + (row * TPAD + (c4 << 2)) * 4;
            const float* s = src + (size_t)row * K + (c4 << 2);
            asm volatile("cp.async.cg.shared.global [%0], [%1], 16;" :: "r"(d), "l"(s));
        }
    }
}

__global__ void __launch_bounds__(256) gemm_mma(
    const float* __restrict__ A, const float* __restrict__ W,
    const float* __restrict__ bias, const float* __restrict__ res,
    const float* __restrict__ pos, float* __restrict__ C,
    int N, int K, int act, int rnd)
{
    extern __shared__ float sm[];
    const int tid = threadIdx.x;
    const int bm = blockIdx.y << 7, bn = blockIdx.x << 7;
    const int wid = tid >> 5, lane = tid & 31;
    const int wm = wid >> 2, wn = wid & 3;
    const int lr = lane >> 2, lc = lane & 3;
    unsigned sbase;
    asm("{ .reg .u64 t; cvta.to.shared.u64 t, %1; cvt.u32.u64 %0, t; }" : "=r"(sbase) : "l"(sm));

    const float* Ab = A + (size_t)bm * K;
    const float* Wb = W + (size_t)bn * K;
    const int NC = K >> 5;

    float acc[4][4][4];
#pragma unroll
    for (int mi = 0; mi < 4; mi++)
#pragma unroll
        for (int ni = 0; ni < 4; ni++)
#pragma unroll
            for (int q = 0; q < 4; q++) acc[mi][ni][q] = 0.f;

    // prologue: fill up to 3 stages
#pragma unroll
    for (int p = 0; p < 3; p++) {
        if (p < NC) {
            load_tile_pair(sbase + p * (STAGEF * 4), Ab, Wb, K, p << 5, tid);
        }
        asm volatile("cp.async.commit_group;" ::: "memory");
    }

    for (int c = 0; c < NC; c++) {
        int rem = NC - 1 - c;
        if (rem >= 2)      asm volatile("cp.async.wait_group 2;" ::: "memory");
        else if (rem == 1) asm volatile("cp.async.wait_group 1;" ::: "memory");
        else               asm volatile("cp.async.wait_group 0;" ::: "memory");
        __syncthreads();

        if (c + 3 < NC) {
            load_tile_pair(sbase + ((c + 3) & 3) * (STAGEF * 4), Ab, Wb, K, (c + 3) << 5, tid);
        }
        asm volatile("cp.async.commit_group;" ::: "memory");

        const float* As = sm + (c & 3) * STAGEF;
        const float* Bs = As + TILEF;
#pragma unroll
        for (int kk = 0; kk < 4; kk++) {
            const int kc = (kk << 3) + lc;
            unsigned af[4][4], bf[4][2];
#pragma unroll
            for (int mi = 0; mi < 4; mi++) {
                const float* ap = As + (wm * 64 + mi * 16 + lr) * TPAD + kc;
                af[mi][0] = __float_as_uint(ap[0]);
                af[mi][1] = __float_as_uint(ap[8 * TPAD]);
                af[mi][2] = __float_as_uint(ap[4]);
                af[mi][3] = __float_as_uint(ap[8 * TPAD + 4]);
            }
#pragma unroll
            for (int ni = 0; ni < 4; ni++) {
                const float* bp = Bs + (wn * 32 + ni * 8 + lr) * TPAD + kc;
                bf[ni][0] = __float_as_uint(bp[0]);
                bf[ni][1] = __float_as_uint(bp[4]);
            }
#pragma unroll
            for (int mi = 0; mi < 4; mi++)
#pragma unroll
                for (int ni = 0; ni < 4; ni++)
                    mma_tf32(acc[mi][ni], af[mi], bf[ni]);
        }
    }

    // ---- epilogue ----
#pragma unroll
    for (int mi = 0; mi < 4; mi++) {
#pragma unroll
        for (int half = 0; half < 2; half++) {
            const int m = bm + wm * 64 + mi * 16 + lr + half * 8;
            float* crow = C + (size_t)m * N;
            const float* rrow = res ? res + (size_t)m * N : nullptr;
            const float* prow = pos ? pos + (size_t)(m % NSEQ) * N : nullptr;
#pragma unroll
            for (int ni = 0; ni < 4; ni++) {
                const int n = bn + wn * 32 + ni * 8 + 2 * lc;
                float v0 = acc[mi][ni][half * 2 + 0];
                float v1 = acc[mi][ni][half * 2 + 1];
                v0 += bias[n]; v1 += bias[n + 1];
                if (act) {
                    v0 = 0.5f * v0 * (1.f + erff(v0 * 0.70710678118654752f));
                    v1 = 0.5f * v1 * (1.f + erff(v1 * 0.70710678118654752f));
                }
                if (prow) { v0 += prow[n]; v1 += prow[n + 1]; }
                if (rrow) { v0 += rrow[n]; v1 += rrow[n + 1]; }
                if (rnd) { v0 = rna_tf32(v0); v1 = rna_tf32(v1); }
                *(float2*)(crow + n) = make_float2(v0, v1);
            }
        }
    }
}

// ---------------- LayerNorm ----------------
__global__ void __launch_bounds__(256) ln_kernel(
    const float* __restrict__ X, const float* __restrict__ w,
    const float* __restrict__ b, float* __restrict__ Y, int rnd)
{
    const int t = blockIdx.x;
    const int tid = threadIdx.x;
    const float* xr = X + (size_t)t * DMODEL;
    float v0 = xr[tid], v1 = xr[tid + 256], v2 = xr[tid + 512];
    float s = v0 + v1 + v2;
    float s2 = v0 * v0 + v1 * v1 + v2 * v2;
#pragma unroll
    for (int o = 16; o > 0; o >>= 1) {
        s += __shfl_xor_sync(0xffffffffu, s, o);
        s2 += __shfl_xor_sync(0xffffffffu, s2, o);
    }
    __shared__ float rs[8], rs2[8];
    __shared__ float mS, rS;
    int wid = tid >> 5, lane = tid & 31;
    if (lane == 0) { rs[wid] = s; rs2[wid] = s2; }
    __syncthreads();
    if (tid == 0) {
        float S = 0.f, S2 = 0.f;
        for (int k = 0; k < 8; k++) { S += rs[k]; S2 += rs2[k]; }
        float m = S * (1.f / 768.f);
        float var = S2 * (1.f / 768.f) - m * m;
        mS = m;
        rS = rsqrtf(var + 1e-5f);
    }
    __syncthreads();
    float m = mS, r = rS;
    float* yr = Y + (size_t)t * DMODEL;
    float o0 = (v0 - m) * r * w[tid] + b[tid];
    float o1 = (v1 - m) * r * w[tid + 256] + b[tid + 256];
    float o2 = (v2 - m) * r * w[tid + 512] + b[tid + 512];
    if (rnd) { o0 = rna_tf32(o0); o1 = rna_tf32(o1); o2 = rna_tf32(o2); }
    yr[tid] = o0; yr[tid + 256] = o1; yr[tid + 512] = o2;
}

// ---------------- fused attention with tf32 mma ----------------
// one CTA per (b,h); keys padded to 224; S=Q@K^T, softmax, O=P@V all in-SMEM.
#define KP    224
#define KSTR  68
#define SSTR  228
#define ATTN_SMEM_FLOATS (KP * KSTR + 64 * SSTR + 64 * KSTR + 64 * SSTR)
#define ATTN_SMEM_BYTES  (ATTN_SMEM_FLOATS * 4)   // 195072

__global__ void __launch_bounds__(256) attn_kernel(
    const float* __restrict__ qkv, float* __restrict__ O)
{
    extern __shared__ float sm[];
    float* Ks = sm;                    // [224][68]  K rows (d contiguous)
    float* Vt = Ks + KP * KSTR;        // [64][228]  V transposed (key contiguous)
    float* Qs = Vt + 64 * SSTR;        // [64][68]   Q tile, pre-scaled
    float* Ss = Qs + 64 * KSTR;        // [64][228]  scores / probs

    const int tid = threadIdx.x;
    const int b = blockIdx.x / NHEAD;
    const int h = blockIdx.x % NHEAD;
    const size_t base = (size_t)b * NSEQ * QKVDIM + h * 64;

    // load K (row-major) and V (transposed); zero pads. qkv is already tf32-rounded.
    for (int idx = tid; idx < KP * 64; idx += 256) {
        int m = idx >> 6, d = idx & 63;
        float kv = 0.f, vv = 0.f;
        if (m < NSEQ) {
            kv = qkv[base + (size_t)m * QKVDIM + 768 + d];
            vv = qkv[base + (size_t)m * QKVDIM + 1536 + d];
        }
        Ks[m * KSTR + d] = kv;
        Vt[d * SSTR + m] = vv;
    }
    __syncthreads();

    const int wid = tid >> 5, lane = tid & 31;
    const int lr = lane >> 2, lc = lane & 3;
    const int wm = wid >> 2, wn = wid & 3;     // 2 x 4 warps

    for (int q0 = 0; q0 < NSEQ; q0 += 64) {
        // Q tile (clamp padded rows; their output never stored). *0.125 is exact.
        for (int idx = tid; idx < 64 * 64; idx += 256) {
            int i = idx >> 6, d = idx & 63;
            int r = q0 + i; if (r > NSEQ - 1) r = NSEQ - 1;
            Qs[i * KSTR + d] = qkv[base + (size_t)r * QKVDIM + d] * 0.125f;
        }
        __syncthreads();

        // ---- S[64][224] = Q @ K^T : warp tile 32(m) x 56(n), K=64 ----
        {
            float acc[2][7][4];
#pragma unroll
            for (int mi = 0; mi < 2; mi++)
#pragma unroll
                for (int ni = 0; ni < 7; ni++)
#pragma unroll
                    for (int q = 0; q < 4; q++) acc[mi][ni][q] = 0.f;
#pragma unroll
            for (int kk = 0; kk < 8; kk++) {
                const int kc = (kk << 3) + lc;
                unsigned af[2][4], bf[7][2];
#pragma unroll
                for (int mi = 0; mi < 2; mi++) {
                    const float* ap = Qs + (wm * 32 + mi * 16 + lr) * KSTR + kc;
                    af[mi][0] = __float_as_uint(ap[0]);
                    af[mi][1] = __float_as_uint(ap[8 * KSTR]);
                    af[mi][2] = __float_as_uint(ap[4]);
                    af[mi][3] = __float_as_uint(ap[8 * KSTR + 4]);
                }
#pragma unroll
                for (int ni = 0; ni < 7; ni++) {
                    const float* bp = Ks + (wn * 56 + ni * 8 + lr) * KSTR + kc;
                    bf[ni][0] = __float_as_uint(bp[0]);
                    bf[ni][1] = __float_as_uint(bp[4]);
                }
#pragma unroll
                for (int mi = 0; mi < 2; mi++)
#pragma unroll
                    for (int ni = 0; ni < 7; ni++)
                        mma_tf32(acc[mi][ni], af[mi], bf[ni]);
            }
#pragma unroll
            for (int mi = 0; mi < 2; mi++) {
                const int r0 = wm * 32 + mi * 16 + lr;
#pragma unroll
                for (int ni = 0; ni < 7; ni++) {
                    const int c0 = wn * 56 + ni * 8 + 2 * lc;
                    Ss[r0 * SSTR + c0]           = acc[mi][ni][0];
                    Ss[r0 * SSTR + c0 + 1]       = acc[mi][ni][1];
                    Ss[(r0 + 8) * SSTR + c0]     = acc[mi][ni][2];
                    Ss[(r0 + 8) * SSTR + c0 + 1] = acc[mi][ni][3];
                }
            }
        }
        __syncthreads();

        // ---- softmax over 196 real keys; probs rounded to tf32; zero pads ----
        for (int row = wid; row < 64; row += 8) {
            float* srow = Ss + row * SSTR;
            float mx = -1e30f;
            for (int m = lane; m < NSEQ; m += 32) mx = fmaxf(mx, srow[m]);
#pragma unroll
            for (int o = 16; o > 0; o >>= 1) mx = fmaxf(mx, __shfl_xor_sync(0xffffffffu, mx, o));
            float sum = 0.f;
            for (int m = lane; m < NSEQ; m += 32) {
                float e = expf(srow[m] - mx);
                srow[m] = e;
                sum += e;
            }
#pragma unroll
            for (int o = 16; o > 0; o >>= 1) sum += __shfl_xor_sync(0xffffffffu, sum, o);
            float inv = 1.f / sum;
            for (int m = lane; m < NSEQ; m += 32) srow[m] = rna_tf32(srow[m] * inv);
            if (lane < KP - NSEQ) srow[NSEQ + lane] = 0.f;
        }
        __syncthreads();

        // ---- O[64][64] = P @ V : warp tile 32(m) x 16(n), K=224 ----
        {
            float acc2[2][2][4];
#pragma unroll
            for (int mi = 0; mi < 2; mi++)
#pragma unroll
                for (int ni = 0; ni < 2; ni++)
#pragma unroll
                    for (int q = 0; q < 4; q++) acc2[mi][ni][q] = 0.f;
#pragma unroll
            for (int kk = 0; kk < 28; kk++) {
                const int kc = (kk << 3) + lc;
                unsigned af[2][4], bf[2][2];
#pragma unroll
                for (int mi = 0; mi < 2; mi++) {
                    const float* ap = Ss + (wm * 32 + mi * 16 + lr) * SSTR + kc;
                    af[mi][0] = __float_as_uint(ap[0]);
                    af[mi][1] = __float_as_uint(ap[8 * SSTR]);
                    af[mi][2] = __float_as_uint(ap[4]);
                    af[mi][3] = __float_as_uint(ap[8 * SSTR + 4]);
                }
#pragma unroll
                for (int ni = 0; ni < 2; ni++) {
                    const float* bp = Vt + (wn * 16 + ni * 8 + lr) * SSTR + kc;
                    bf[ni][0] = __float_as_uint(bp[0]);
                    bf[ni][1] = __float_as_uint(bp[4]);
                }
#pragma unroll
                for (int mi = 0; mi < 2; mi++)
#pragma unroll
                    for (int ni = 0; ni < 2; ni++)
                        mma_tf32(acc2[mi][ni], af[mi], bf[ni]);
            }
#pragma unroll
            for (int mi = 0; mi < 2; mi++) {
#pragma unroll
                for (int half = 0; half < 2; half++) {
                    const int r = q0 + wm * 32 + mi * 16 + lr + half * 8;
                    if (r < NSEQ) {
                        float* orow = O + (size_t)(b * NSEQ + r) * DMODEL + h * 64;
#pragma unroll
                        for (int ni = 0; ni < 2; ni++) {
                            const int n = wn * 16 + ni * 8 + 2 * lc;
                            orow[n]     = rna_tf32(acc2[mi][ni][half * 2 + 0]);
                            orow[n + 1] = rna_tf32(acc2[mi][ni][half * 2 + 1]);
                        }
                    }
                }
            }
        }
        __syncthreads();
    }
}

// ---------------- launch ----------------
extern "C" void kernel_launch(void* const* d_in, const int* in_sizes, int n_in,
                              void* d_out, int out_size)
{
    const float* x       = (const float*)d_in[0];
    const float* patch_w = (const float*)d_in[1];
    const float* patch_b = (const float*)d_in[2];
    const float* pos     = (const float*)d_in[3];
    const float* ln1_w   = (const float*)d_in[4];
    const float* ln1_b   = (const float*)d_in[5];
    const float* qkv_w   = (const float*)d_in[6];
    const float* qkv_b   = (const float*)d_in[7];
    const float* proj_w  = (const float*)d_in[8];
    const float* proj_b  = (const float*)d_in[9];
    const float* ln2_w   = (const float*)d_in[10];
    const float* ln2_b   = (const float*)d_in[11];
    const float* fc1_w   = (const float*)d_in[12];
    const float* fc1_b   = (const float*)d_in[13];
    const float* fc2_w   = (const float*)d_in[14];
    const float* fc2_b   = (const float*)d_in[15];
    const float* lnf_w   = (const float*)d_in[16];
    const float* lnf_b   = (const float*)d_in[17];

    float *h, *y, *qkv, *o, *ff, *im, *w;
    cudaGetSymbolAddress((void**)&h,   g_h);
    cudaGetSymbolAddress((void**)&y,   g_y);
    cudaGetSymbolAddress((void**)&qkv, g_qkv);
    cudaGetSymbolAddress((void**)&o,   g_o);
    cudaGetSymbolAddress((void**)&ff,  g_ff);
    cudaGetSymbolAddress((void**)&im,  g_im);
    cudaGetSymbolAddress((void**)&w,   g_w);

    cudaFuncSetAttribute(attn_kernel, cudaFuncAttributeMaxDynamicSharedMemorySize, ATTN_SMEM_BYTES);
    cudaFuncSetAttribute(gemm_mma, cudaFuncAttributeMaxDynamicSharedMemorySize, GSMEM);

    // round weights to tf32 (rna) into scratch
    cvt_kernel<<<(21233664/4 + 255)/256, 256>>>((const float4*)qkv_w,  (float4*)(w + OQKV),   21233664/4);
    cvt_kernel<<<( 7077888/4 + 255)/256, 256>>>((const float4*)proj_w, (float4*)(w + OPROJ),   7077888/4);
    cvt_kernel<<<(28311552/4 + 255)/256, 256>>>((const float4*)fc1_w,  (float4*)(w + OFC1),   28311552/4);
    cvt_kernel<<<(28311552/4 + 255)/256, 256>>>((const float4*)fc2_w,  (float4*)(w + OFC2),   28311552/4);
    cvt_kernel<<<(  589824/4 + 255)/256, 256>>>((const float4*)patch_w,(float4*)(w + OPATCH),   589824/4);

    im2col_kernel<<<(NTOK * DMODEL + 255) / 256, 256>>>(x, im);
    gemm_mma<<<dim3(DMODEL / 128, NTOK / 128), 256, GSMEM>>>(
        im, w + OPATCH, patch_b, nullptr, pos, h, DMODEL, DMODEL, 0, 0);

    for (int l = 0; l < NLAYER; l++) {
        ln_kernel<<<NTOK, 256>>>(h, ln1_w + l * DMODEL, ln1_b + l * DMODEL, y, 1);
        // qkv output tf32-rounded (rnd=1): feeds mma attention directly
        gemm_mma<<<dim3(QKVDIM / 128, NTOK / 128), 256, GSMEM>>>(
            y, w + OQKV + (size_t)l * QKVDIM * DMODEL, qkv_b + l * QKVDIM,
            nullptr, nullptr, qkv, QKVDIM, DMODEL, 0, 1);
        attn_kernel<<<32 * NHEAD, 256, ATTN_SMEM_BYTES>>>(qkv, o);
        gemm_mma<<<dim3(DMODEL / 128, NTOK / 128), 256, GSMEM>>>(
            o, w + OPROJ + (size_t)l * DMODEL * DMODEL, proj_b + l * DMODEL,
            h, nullptr, h, DMODEL, DMODEL, 0, 0);
        ln_kernel<<<NTOK, 256>>>(h, ln2_w + l * DMODEL, ln2_b + l * DMODEL, y, 1);
        gemm_mma<<<dim3(FFDIM / 128, NTOK / 128), 256, GSMEM>>>(
            y, w + OFC1 + (size_t)l * FFDIM * DMODEL, fc1_b + l * FFDIM,
            nullptr, nullptr, ff, FFDIM, DMODEL, 1, 1);
        gemm_mma<<<dim3(DMODEL / 128, NTOK / 128), 256, GSMEM>>>(
            ff, w + OFC2 + (size_t)l * DMODEL * FFDIM, fc2_b + l * DMODEL,
            h, nullptr, h, DMODEL, FFDIM, 0, 0);
    }
    ln_kernel<<<NTOK, 256>>>(h, lnf_w, lnf_b, (float*)d_out, 0);
}

// round 6
// speedup vs baseline: 2.9421x; 1.1081x over previous
#include <cuda_runtime.h>
#include <math.h>

// ---------------- problem constants ----------------
#define NTOK   6272
#define DMODEL 768
#define FFDIM  3072
#define QKVDIM 2304
#define NHEAD  12
#define NSEQ   196
#define NLAYER 12

// ---------------- weight scratch offsets (floats) ----------------
#define OQKV   0
#define OPROJ  21233664
#define OFC1   28311552
#define OFC2   56623104
#define OPATCH 84934656
#define WTOTAL 85524480

__device__ __align__(256) float g_w  [WTOTAL];
__device__ __align__(256) float g_h  [NTOK * DMODEL];
__device__ __align__(256) float g_y  [NTOK * DMODEL];
__device__ __align__(256) float g_qkv[NTOK * QKVDIM];
__device__ __align__(256) float g_o  [NTOK * DMODEL];
__device__ __align__(256) float g_ff [NTOK * FFDIM];
__device__ __align__(256) float g_im [NTOK * DMODEL];

// ---------------- helpers ----------------
__device__ __forceinline__ float rna_tf32(float x) {
    unsigned u; asm("cvt.rna.tf32.f32 %0, %1;" : "=r"(u) : "f"(x));
    return __uint_as_float(u);
}
__device__ __forceinline__ void mma_tf32(float* c, const unsigned* a, const unsigned* b) {
    asm volatile("mma.sync.aligned.m16n8k8.row.col.f32.tf32.tf32.f32 "
        "{%0,%1,%2,%3}, {%4,%5,%6,%7}, {%8,%9}, {%0,%1,%2,%3};"
        : "+f"(c[0]), "+f"(c[1]), "+f"(c[2]), "+f"(c[3])
        : "r"(a[0]), "r"(a[1]), "r"(a[2]), "r"(a[3]), "r"(b[0]), "r"(b[1]));
}

// ---------------- weight tf32-rounding pass ----------------
__global__ void cvt_kernel(const float4* __restrict__ s, float4* __restrict__ d, int n4) {
    int i = blockIdx.x * 256 + threadIdx.x;
    if (i >= n4) return;
    float4 v = s[i];
    v.x = rna_tf32(v.x); v.y = rna_tf32(v.y); v.z = rna_tf32(v.z); v.w = rna_tf32(v.w);
    d[i] = v;
}

// ---------------- im2col (rounds to tf32) ----------------
__global__ void im2col_kernel(const float* __restrict__ x, float* __restrict__ out) {
    int idx = blockIdx.x * 256 + threadIdx.x;
    if (idx >= NTOK * DMODEL) return;
    int t = idx / 768, r = idx % 768;
    int c = r >> 8;
    int ij = r & 255;
    int i = ij >> 4, j = ij & 15;
    int b = t / 196, p = t % 196;
    int py = p / 14, px = p % 14;
    out[idx] = rna_tf32(x[((size_t)(b * 3 + c) * 224 + py * 16 + i) * 224 + px * 16 + j]);
}

// ---------------- tf32 mma.sync GEMM: C[M,N] = A[M,K] @ W[N,K]^T (+epilogue) ----------------
// 128x128x32 tile, 256 threads (8 warps 2x4), warp tile 64x32, 3-stage cp.async, 2 CTAs/SM.
#define TPAD   36
#define TILEF  (128 * TPAD)
#define STAGEF (2 * TILEF)
#define GSMEM  (3 * STAGEF * 4)        // 110592 bytes -> 2 CTAs/SM

__device__ __forceinline__ void load_tile_pair(unsigned sdst, const float* __restrict__ Ab,
                                               const float* __restrict__ Wb, int K, int k0, int tid)
{
#pragma unroll
    for (int half = 0; half < 2; half++) {
        const float* src = (half ? Wb : Ab) + k0;
        unsigned base = sdst + half * (TILEF * 4);
#pragma unroll
        for (int j = 0; j < 4; j++) {
            int i = (j << 8) + tid;
            int row = i >> 3, c4 = i & 7;
            unsigned d = base + (row * TPAD + (c4 << 2)) * 4;
            const float* s = src + (size_t)row * K + (c4 << 2);
            asm volatile("cp.async.cg.shared.global [%0], [%1], 16;" :: "r"(d), "l"(s));
        }
    }
}

__global__ void __launch_bounds__(256, 2) gemm_mma(
    const float* __restrict__ A, const float* __restrict__ W,
    const float* __restrict__ bias, const float* __restrict__ res,
    const float* __restrict__ pos, float* __restrict__ C,
    int N, int K, int act, int rnd)
{
    extern __shared__ float sm[];
    const int tid = threadIdx.x;
    const int bm = blockIdx.y << 7, bn = blockIdx.x << 7;
    const int wid = tid >> 5, lane = tid & 31;
    const int wm = wid >> 2, wn = wid & 3;
    const int lr = lane >> 2, lc = lane & 3;
    unsigned sbase;
    asm("{ .reg .u64 t; cvta.to.shared.u64 t, %1; cvt.u32.u64 %0, t; }" : "=r"(sbase) : "l"(sm));

    const float* Ab = A + (size_t)bm * K;
    const float* Wb = W + (size_t)bn * K;
    const int NC = K >> 5;

    float acc[4][4][4];
#pragma unroll
    for (int mi = 0; mi < 4; mi++)
#pragma unroll
        for (int ni = 0; ni < 4; ni++)
#pragma unroll
            for (int q = 0; q < 4; q++) acc[mi][ni][q] = 0.f;

    // prologue: stages 0,1
    load_tile_pair(sbase, Ab, Wb, K, 0, tid);
    asm volatile("cp.async.commit_group;" ::: "memory");
    load_tile_pair(sbase + STAGEF * 4, Ab, Wb, K, 32, tid);
    asm volatile("cp.async.commit_group;" ::: "memory");

    for (int c = 0; c < NC; c++) {
        // one commit per iteration (possibly empty) keeps group accounting uniform
        if (c + 2 < NC)
            load_tile_pair(sbase + ((c + 2) % 3) * (STAGEF * 4), Ab, Wb, K, (c + 2) << 5, tid);
        asm volatile("cp.async.commit_group;" ::: "memory");
        asm volatile("cp.async.wait_group 2;" ::: "memory");   // chunk c resident
        __syncthreads();

        const float* As = sm + (c % 3) * STAGEF;
        const float* Bs = As + TILEF;
#pragma unroll
        for (int kk = 0; kk < 4; kk++) {
            const int kc = (kk << 3) + lc;
            unsigned af[4][4], bf[4][2];
#pragma unroll
            for (int mi = 0; mi < 4; mi++) {
                const float* ap = As + (wm * 64 + mi * 16 + lr) * TPAD + kc;
                af[mi][0] = __float_as_uint(ap[0]);
                af[mi][1] = __float_as_uint(ap[8 * TPAD]);
                af[mi][2] = __float_as_uint(ap[4]);
                af[mi][3] = __float_as_uint(ap[8 * TPAD + 4]);
            }
#pragma unroll
            for (int ni = 0; ni < 4; ni++) {
                const float* bp = Bs + (wn * 32 + ni * 8 + lr) * TPAD + kc;
                bf[ni][0] = __float_as_uint(bp[0]);
                bf[ni][1] = __float_as_uint(bp[4]);
            }
#pragma unroll
            for (int mi = 0; mi < 4; mi++)
#pragma unroll
                for (int ni = 0; ni < 4; ni++)
                    mma_tf32(acc[mi][ni], af[mi], bf[ni]);
        }
        __syncthreads();   // protect slot (c%3) before it is overwritten at c+1's load of c+2? (c+2)%3 != c%3, but c+3 reuses; barrier keeps warps within 1 chunk
    }

    // ---- epilogue ----
#pragma unroll
    for (int mi = 0; mi < 4; mi++) {
#pragma unroll
        for (int half = 0; half < 2; half++) {
            const int m = bm + wm * 64 + mi * 16 + lr + half * 8;
            float* crow = C + (size_t)m * N;
            const float* rrow = res ? res + (size_t)m * N : nullptr;
            const float* prow = pos ? pos + (size_t)(m % NSEQ) * N : nullptr;
#pragma unroll
            for (int ni = 0; ni < 4; ni++) {
                const int n = bn + wn * 32 + ni * 8 + 2 * lc;
                float v0 = acc[mi][ni][half * 2 + 0];
                float v1 = acc[mi][ni][half * 2 + 1];
                v0 += bias[n]; v1 += bias[n + 1];
                if (act) {
                    v0 = 0.5f * v0 * (1.f + erff(v0 * 0.70710678118654752f));
                    v1 = 0.5f * v1 * (1.f + erff(v1 * 0.70710678118654752f));
                }
                if (prow) { v0 += prow[n]; v1 += prow[n + 1]; }
                if (rrow) { v0 += rrow[n]; v1 += rrow[n + 1]; }
                if (rnd) { v0 = rna_tf32(v0); v1 = rna_tf32(v1); }
                *(float2*)(crow + n) = make_float2(v0, v1);
            }
        }
    }
}

// ---------------- LayerNorm ----------------
__global__ void __launch_bounds__(256) ln_kernel(
    const float* __restrict__ X, const float* __restrict__ w,
    const float* __restrict__ b, float* __restrict__ Y, int rnd)
{
    const int t = blockIdx.x;
    const int tid = threadIdx.x;
    const float* xr = X + (size_t)t * DMODEL;
    float v0 = xr[tid], v1 = xr[tid + 256], v2 = xr[tid + 512];
    float s = v0 + v1 + v2;
    float s2 = v0 * v0 + v1 * v1 + v2 * v2;
#pragma unroll
    for (int o = 16; o > 0; o >>= 1) {
        s += __shfl_xor_sync(0xffffffffu, s, o);
        s2 += __shfl_xor_sync(0xffffffffu, s2, o);
    }
    __shared__ float rs[8], rs2[8];
    __shared__ float mS, rS;
    int wid = tid >> 5, lane = tid & 31;
    if (lane == 0) { rs[wid] = s; rs2[wid] = s2; }
    __syncthreads();
    if (tid == 0) {
        float S = 0.f, S2 = 0.f;
        for (int k = 0; k < 8; k++) { S += rs[k]; S2 += rs2[k]; }
        float m = S * (1.f / 768.f);
        float var = S2 * (1.f / 768.f) - m * m;
        mS = m;
        rS = rsqrtf(var + 1e-5f);
    }
    __syncthreads();
    float m = mS, r = rS;
    float* yr = Y + (size_t)t * DMODEL;
    float o0 = (v0 - m) * r * w[tid] + b[tid];
    float o1 = (v1 - m) * r * w[tid + 256] + b[tid + 256];
    float o2 = (v2 - m) * r * w[tid + 512] + b[tid + 512];
    if (rnd) { o0 = rna_tf32(o0); o1 = rna_tf32(o1); o2 = rna_tf32(o2); }
    yr[tid] = o0; yr[tid + 256] = o1; yr[tid + 512] = o2;
}

// ---------------- fused attention with tf32 mma ----------------
#define KP    224
#define KSTR  68
#define SSTR  228
#define ATTN_SMEM_FLOATS (KP * KSTR + 64 * SSTR + 64 * KSTR + 64 * SSTR)
#define ATTN_SMEM_BYTES  (ATTN_SMEM_FLOATS * 4)   // 195072

__global__ void __launch_bounds__(256) attn_kernel(
    const float* __restrict__ qkv, float* __restrict__ O)
{
    extern __shared__ float sm[];
    float* Ks = sm;                    // [224][68]
    float* Vt = Ks + KP * KSTR;        // [64][228]
    float* Qs = Vt + 64 * SSTR;        // [64][68]
    float* Ss = Qs + 64 * KSTR;        // [64][228]

    const int tid = threadIdx.x;
    const int b = blockIdx.x / NHEAD;
    const int h = blockIdx.x % NHEAD;
    const size_t base = (size_t)b * NSEQ * QKVDIM + h * 64;

    for (int idx = tid; idx < KP * 64; idx += 256) {
        int m = idx >> 6, d = idx & 63;
        float kv = 0.f, vv = 0.f;
        if (m < NSEQ) {
            kv = qkv[base + (size_t)m * QKVDIM + 768 + d];
            vv = qkv[base + (size_t)m * QKVDIM + 1536 + d];
        }
        Ks[m * KSTR + d] = kv;
        Vt[d * SSTR + m] = vv;
    }
    __syncthreads();

    const int wid = tid >> 5, lane = tid & 31;
    const int lr = lane >> 2, lc = lane & 3;
    const int wm = wid >> 2, wn = wid & 3;

    for (int q0 = 0; q0 < NSEQ; q0 += 64) {
        for (int idx = tid; idx < 64 * 64; idx += 256) {
            int i = idx >> 6, d = idx & 63;
            int r = q0 + i; if (r > NSEQ - 1) r = NSEQ - 1;
            Qs[i * KSTR + d] = qkv[base + (size_t)r * QKVDIM + d] * 0.125f;
        }
        __syncthreads();

        {
            float acc[2][7][4];
#pragma unroll
            for (int mi = 0; mi < 2; mi++)
#pragma unroll
                for (int ni = 0; ni < 7; ni++)
#pragma unroll
                    for (int q = 0; q < 4; q++) acc[mi][ni][q] = 0.f;
#pragma unroll
            for (int kk = 0; kk < 8; kk++) {
                const int kc = (kk << 3) + lc;
                unsigned af[2][4], bf[7][2];
#pragma unroll
                for (int mi = 0; mi < 2; mi++) {
                    const float* ap = Qs + (wm * 32 + mi * 16 + lr) * KSTR + kc;
                    af[mi][0] = __float_as_uint(ap[0]);
                    af[mi][1] = __float_as_uint(ap[8 * KSTR]);
                    af[mi][2] = __float_as_uint(ap[4]);
                    af[mi][3] = __float_as_uint(ap[8 * KSTR + 4]);
                }
#pragma unroll
                for (int ni = 0; ni < 7; ni++) {
                    const float* bp = Ks + (wn * 56 + ni * 8 + lr) * KSTR + kc;
                    bf[ni][0] = __float_as_uint(bp[0]);
                    bf[ni][1] = __float_as_uint(bp[4]);
                }
#pragma unroll
                for (int mi = 0; mi < 2; mi++)
#pragma unroll
                    for (int ni = 0; ni < 7; ni++)
                        mma_tf32(acc[mi][ni], af[mi], bf[ni]);
            }
#pragma unroll
            for (int mi = 0; mi < 2; mi++) {
                const int r0 = wm * 32 + mi * 16 + lr;
#pragma unroll
                for (int ni = 0; ni < 7; ni++) {
                    const int c0 = wn * 56 + ni * 8 + 2 * lc;
                    Ss[r0 * SSTR + c0]           = acc[mi][ni][0];
                    Ss[r0 * SSTR + c0 + 1]       = acc[mi][ni][1];
                    Ss[(r0 + 8) * SSTR + c0]     = acc[mi][ni][2];
                    Ss[(r0 + 8) * SSTR + c0 + 1] = acc[mi][ni][3];
                }
            }
        }
        __syncthreads();

        for (int row = wid; row < 64; row += 8) {
            float* srow = Ss + row * SSTR;
            float mx = -1e30f;
            for (int m = lane; m < NSEQ; m += 32) mx = fmaxf(mx, srow[m]);
#pragma unroll
            for (int o = 16; o > 0; o >>= 1) mx = fmaxf(mx, __shfl_xor_sync(0xffffffffu, mx, o));
            float sum = 0.f;
            for (int m = lane; m < NSEQ; m += 32) {
                float e = expf(srow[m] - mx);
                srow[m] = e;
                sum += e;
            }
#pragma unroll
            for (int o = 16; o > 0; o >>= 1) sum += __shfl_xor_sync(0xffffffffu, sum, o);
            float inv = 1.f / sum;
            for (int m = lane; m < NSEQ; m += 32) srow[m] = rna_tf32(srow[m] * inv);
            if (lane < KP - NSEQ) srow[NSEQ + lane] = 0.f;
        }
        __syncthreads();

        {
            float acc2[2][2][4];
#pragma unroll
            for (int mi = 0; mi < 2; mi++)
#pragma unroll
                for (int ni = 0; ni < 2; ni++)
#pragma unroll
                    for (int q = 0; q < 4; q++) acc2[mi][ni][q] = 0.f;
#pragma unroll
            for (int kk = 0; kk < 28; kk++) {
                const int kc = (kk << 3) + lc;
                unsigned af[2][4], bf[2][2];
#pragma unroll
                for (int mi = 0; mi < 2; mi++) {
                    const float* ap = Ss + (wm * 32 + mi * 16 + lr) * SSTR + kc;
                    af[mi][0] = __float_as_uint(ap[0]);
                    af[mi][1] = __float_as_uint(ap[8 * SSTR]);
                    af[mi][2] = __float_as_uint(ap[4]);
                    af[mi][3] = __float_as_uint(ap[8 * SSTR + 4]);
                }
#pragma unroll
                for (int ni = 0; ni < 2; ni++) {
                    const float* bp = Vt + (wn * 16 + ni * 8 + lr) * SSTR + kc;
                    bf[ni][0] = __float_as_uint(bp[0]);
                    bf[ni][1] = __float_as_uint(bp[4]);
                }
#pragma unroll
                for (int mi = 0; mi < 2; mi++)
#pragma unroll
                    for (int ni = 0; ni < 2; ni++)
                        mma_tf32(acc2[mi][ni], af[mi], bf[ni]);
            }
#pragma unroll
            for (int mi = 0; mi < 2; mi++) {
#pragma unroll
                for (int half = 0; half < 2; half++) {
                    const int r = q0 + wm * 32 + mi * 16 + lr + half * 8;
                    if (r < NSEQ) {
                        float* orow = O + (size_t)(b * NSEQ + r) * DMODEL + h * 64;
#pragma unroll
                        for (int ni = 0; ni < 2; ni++) {
                            const int n = wn * 16 + ni * 8 + 2 * lc;
                            orow[n]     = rna_tf32(acc2[mi][ni][half * 2 + 0]);
                            orow[n + 1] = rna_tf32(acc2[mi][ni][half * 2 + 1]);
                        }
                    }
                }
            }
        }
        __syncthreads();
    }
}

// ---------------- launch ----------------
extern "C" void kernel_launch(void* const* d_in, const int* in_sizes, int n_in,
                              void* d_out, int out_size)
{
    const float* x       = (const float*)d_in[0];
    const float* patch_w = (const float*)d_in[1];
    const float* patch_b = (const float*)d_in[2];
    const float* pos     = (const float*)d_in[3];
    const float* ln1_w   = (const float*)d_in[4];
    const float* ln1_b   = (const float*)d_in[5];
    const float* qkv_w   = (const float*)d_in[6];
    const float* qkv_b   = (const float*)d_in[7];
    const float* proj_w  = (const float*)d_in[8];
    const float* proj_b  = (const float*)d_in[9];
    const float* ln2_w   = (const float*)d_in[10];
    const float* ln2_b   = (const float*)d_in[11];
    const float* fc1_w   = (const float*)d_in[12];
    const float* fc1_b   = (const float*)d_in[13];
    const float* fc2_w   = (const float*)d_in[14];
    const float* fc2_b   = (const float*)d_in[15];
    const float* lnf_w   = (const float*)d_in[16];
    const float* lnf_b   = (const float*)d_in[17];

    float *h, *y, *qkv, *o, *ff, *im, *w;
    cudaGetSymbolAddress((void**)&h,   g_h);
    cudaGetSymbolAddress((void**)&y,   g_y);
    cudaGetSymbolAddress((void**)&qkv, g_qkv);
    cudaGetSymbolAddress((void**)&o,   g_o);
    cudaGetSymbolAddress((void**)&ff,  g_ff);
    cudaGetSymbolAddress((void**)&im,  g_im);
    cudaGetSymbolAddress((void**)&w,   g_w);

    cudaFuncSetAttribute(attn_kernel, cudaFuncAttributeMaxDynamicSharedMemorySize, ATTN_SMEM_BYTES);
    cudaFuncSetAttribute(gemm_mma, cudaFuncAttributeMaxDynamicSharedMemorySize, GSMEM);

    // launches ordered so index 5 (ncu -s 5 -c 1) = gemm_mma (patch embed GEMM)
    cvt_kernel<<<(21233664/4 + 255)/256, 256>>>((const float4*)qkv_w,  (float4*)(w + OQKV),   21233664/4);  // 0
    cvt_kernel<<<( 7077888/4 + 255)/256, 256>>>((const float4*)proj_w, (float4*)(w + OPROJ),   7077888/4);  // 1
    cvt_kernel<<<(28311552/4 + 255)/256, 256>>>((const float4*)fc1_w,  (float4*)(w + OFC1),   28311552/4);  // 2
    cvt_kernel<<<(  589824/4 + 255)/256, 256>>>((const float4*)patch_w,(float4*)(w + OPATCH),   589824/4);  // 3
    im2col_kernel<<<(NTOK * DMODEL + 255) / 256, 256>>>(x, im);                                             // 4
    gemm_mma<<<dim3(DMODEL / 128, NTOK / 128), 256, GSMEM>>>(                                               // 5 <- profiled
        im, w + OPATCH, patch_b, nullptr, pos, h, DMODEL, DMODEL, 0, 0);
    cvt_kernel<<<(28311552/4 + 255)/256, 256>>>((const float4*)fc2_w,  (float4*)(w + OFC2),   28311552/4);  // 6

    for (int l = 0; l < NLAYER; l++) {
        ln_kernel<<<NTOK, 256>>>(h, ln1_w + l * DMODEL, ln1_b + l * DMODEL, y, 1);
        gemm_mma<<<dim3(QKVDIM / 128, NTOK / 128), 256, GSMEM>>>(
            y, w + OQKV + (size_t)l * QKVDIM * DMODEL, qkv_b + l * QKVDIM,
            nullptr, nullptr, qkv, QKVDIM, DMODEL, 0, 1);
        attn_kernel<<<32 * NHEAD, 256, ATTN_SMEM_BYTES>>>(qkv, o);
        gemm_mma<<<dim3(DMODEL / 128, NTOK / 128), 256, GSMEM>>>(
            o, w + OPROJ + (size_t)l * DMODEL * DMODEL, proj_b + l * DMODEL,
            h, nullptr, h, DMODEL, DMODEL, 0, 0);
        ln_kernel<<<NTOK, 256>>>(h, ln2_w + l * DMODEL, ln2_b + l * DMODEL, y, 1);
        gemm_mma<<<dim3(FFDIM / 128, NTOK / 128), 256, GSMEM>>>(
            y, w + OFC1 + (size_t)l * FFDIM * DMODEL, fc1_b + l * FFDIM,
            nullptr, nullptr, ff, FFDIM, DMODEL, 1, 1);
        gemm_mma<<<dim3(DMODEL / 128, NTOK / 128), 256, GSMEM>>>(
            ff, w + OFC2 + (size_t)l * DMODEL * FFDIM, fc2_b + l * DMODEL,
            h, nullptr, h, DMODEL, FFDIM, 0, 0);
    }
    ln_kernel<<<NTOK, 256>>>(h, lnf_w, lnf_b, (float*)d_out, 0);
}

// round 7
// speedup vs baseline: 4.6960x; 1.5962x over previous
#include <cuda_runtime.h>
#include <cuda_fp16.h>
#include <math.h>

// ---------------- problem constants ----------------
#define NTOK   6272
#define DMODEL 768
#define FFDIM  3072
#define QKVDIM 2304
#define NHEAD  12
#define NSEQ   196
#define NLAYER 12

// ---------------- weight scratch offsets (half elements) ----------------
#define OQKV   0
#define OPROJ  21233664
#define OFC1   28311552
#define OFC2   56623104
#define OPATCH 84934656
#define WTOTAL 85524480

__device__ __align__(256) __half g_w  [WTOTAL];
__device__ __align__(256) float  g_h  [NTOK * DMODEL];   // residual stream fp32
__device__ __align__(256) __half g_y  [NTOK * DMODEL];
__device__ __align__(256) __half g_qkv[NTOK * QKVDIM];
__device__ __align__(256) __half g_o  [NTOK * DMODEL];
__device__ __align__(256) __half g_ff [NTOK * FFDIM];
__device__ __align__(256) __half g_im [NTOK * DMODEL];

// ---------------- helpers ----------------
__device__ __forceinline__ void mma_f16(float* c, const unsigned* a, const unsigned* b) {
    asm volatile("mma.sync.aligned.m16n8k16.row.col.f32.f16.f16.f32 "
        "{%0,%1,%2,%3}, {%4,%5,%6,%7}, {%8,%9}, {%0,%1,%2,%3};"
        : "+f"(c[0]), "+f"(c[1]), "+f"(c[2]), "+f"(c[3])
        : "r"(a[0]), "r"(a[1]), "r"(a[2]), "r"(a[3]), "r"(b[0]), "r"(b[1]));
}

// ---------------- weight f32 -> f16 pass ----------------
__global__ void cvt_kernel(const float4* __restrict__ s, __half2* __restrict__ d, int n4) {
    int i = blockIdx.x * 256 + threadIdx.x;
    if (i >= n4) return;
    float4 v = s[i];
    d[2 * i]     = __floats2half2_rn(v.x, v.y);
    d[2 * i + 1] = __floats2half2_rn(v.z, v.w);
}

// ---------------- im2col -> f16 ----------------
__global__ void im2col_kernel(const float* __restrict__ x, __half* __restrict__ out) {
    int idx = blockIdx.x * 256 + threadIdx.x;
    if (idx >= NTOK * DMODEL) return;
    int t = idx / 768, r = idx % 768;
    int c = r >> 8;
    int ij = r & 255;
    int i = ij >> 4, j = ij & 15;
    int b = t / 196, p = t % 196;
    int py = p / 14, px = p % 14;
    out[idx] = __float2half_rn(x[((size_t)(b * 3 + c) * 224 + py * 16 + i) * 224 + px * 16 + j]);
}

// ---------------- fp16 mma GEMM: C[M,N] = A[M,K] @ W[N,K]^T (+epilogue) ----------------
// 128x128x32 tile, 256 threads (8 warps 2x4), warp tile 64x32, 3-stage cp.async, 2 CTAs/SM.
#define TPADH  40                      // halves; 40*2B=80B rows (16B-aligned, conflict-free frags)
#define TILEH  (128 * TPADH)
#define STAGEH (2 * TILEH)
#define GSMEM  (3 * STAGEH * 2)        // 61440 bytes

__device__ __forceinline__ void load_tile_pair(unsigned sdst, const __half* __restrict__ Ab,
                                               const __half* __restrict__ Wb, int K, int k0, int tid)
{
#pragma unroll
    for (int half_ = 0; half_ < 2; half_++) {
        const __half* src = (half_ ? Wb : Ab) + k0;
        unsigned base = sdst + half_ * (TILEH * 2);
#pragma unroll
        for (int j = 0; j < 2; j++) {
            int i = (j << 8) + tid;            // 0..511 16B segments
            int row = i >> 2, c16 = i & 3;
            unsigned d = base + (row * TPADH + (c16 << 3)) * 2;
            const __half* s = src + (size_t)row * K + (c16 << 3);
            asm volatile("cp.async.cg.shared.global [%0], [%1], 16;" :: "r"(d), "l"(s));
        }
    }
}

__global__ void __launch_bounds__(256, 2) gemm_mma(
    const __half* __restrict__ A, const __half* __restrict__ W,
    const float* __restrict__ bias, const float* __restrict__ res,
    const float* __restrict__ pos, float* __restrict__ Cf,
    __half* __restrict__ Ch, int N, int K, int act)
{
    extern __shared__ __half smh[];
    const int tid = threadIdx.x;
    const int bm = blockIdx.y << 7, bn = blockIdx.x << 7;
    const int wid = tid >> 5, lane = tid & 31;
    const int wm = wid >> 2, wn = wid & 3;
    const int lr = lane >> 2, lc = lane & 3;
    unsigned sbase;
    asm("{ .reg .u64 t; cvta.to.shared.u64 t, %1; cvt.u32.u64 %0, t; }" : "=r"(sbase) : "l"(smh));

    const __half* Ab = A + (size_t)bm * K;
    const __half* Wb = W + (size_t)bn * K;
    const int NC = K >> 5;

    float acc[4][4][4];
#pragma unroll
    for (int mi = 0; mi < 4; mi++)
#pragma unroll
        for (int ni = 0; ni < 4; ni++)
#pragma unroll
            for (int q = 0; q < 4; q++) acc[mi][ni][q] = 0.f;

    load_tile_pair(sbase, Ab, Wb, K, 0, tid);
    asm volatile("cp.async.commit_group;" ::: "memory");
    load_tile_pair(sbase + STAGEH * 2, Ab, Wb, K, 32, tid);
    asm volatile("cp.async.commit_group;" ::: "memory");

    for (int c = 0; c < NC; c++) {
        if (c + 2 < NC)
            load_tile_pair(sbase + ((c + 2) % 3) * (STAGEH * 2), Ab, Wb, K, (c + 2) << 5, tid);
        asm volatile("cp.async.commit_group;" ::: "memory");
        asm volatile("cp.async.wait_group 2;" ::: "memory");
        __syncthreads();

        const __half* As = smh + (c % 3) * STAGEH;
        const __half* Bs = As + TILEH;
#pragma unroll
        for (int kk = 0; kk < 2; kk++) {
            const int koff = (kk << 4) + (lc << 1);
            unsigned af[4][4], bf[4][2];
#pragma unroll
            for (int mi = 0; mi < 4; mi++) {
                const __half* ap = As + (wm * 64 + mi * 16 + lr) * TPADH + koff;
                af[mi][0] = *(const unsigned*)(ap);
                af[mi][1] = *(const unsigned*)(ap + 8 * TPADH);
                af[mi][2] = *(const unsigned*)(ap + 8);
                af[mi][3] = *(const unsigned*)(ap + 8 * TPADH + 8);
            }
#pragma unroll
            for (int ni = 0; ni < 4; ni++) {
                const __half* bp = Bs + (wn * 32 + ni * 8 + lr) * TPADH + koff;
                bf[ni][0] = *(const unsigned*)(bp);
                bf[ni][1] = *(const unsigned*)(bp + 8);
            }
#pragma unroll
            for (int mi = 0; mi < 4; mi++)
#pragma unroll
                for (int ni = 0; ni < 4; ni++)
                    mma_f16(acc[mi][ni], af[mi], bf[ni]);
        }
        __syncthreads();
    }

    // ---- epilogue: fp32 math, output fp32 (Cf) or fp16 (Ch) ----
#pragma unroll
    for (int mi = 0; mi < 4; mi++) {
#pragma unroll
        for (int half_ = 0; half_ < 2; half_++) {
            const int m = bm + wm * 64 + mi * 16 + lr + half_ * 8;
            const float* rrow = res ? res + (size_t)m * N : nullptr;
            const float* prow = pos ? pos + (size_t)(m % NSEQ) * N : nullptr;
#pragma unroll
            for (int ni = 0; ni < 4; ni++) {
                const int n = bn + wn * 32 + ni * 8 + 2 * lc;
                float v0 = acc[mi][ni][half_ * 2 + 0];
                float v1 = acc[mi][ni][half_ * 2 + 1];
                v0 += bias[n]; v1 += bias[n + 1];
                if (act) {
                    v0 = 0.5f * v0 * (1.f + erff(v0 * 0.70710678118654752f));
                    v1 = 0.5f * v1 * (1.f + erff(v1 * 0.70710678118654752f));
                }
                if (prow) { v0 += prow[n]; v1 += prow[n + 1]; }
                if (rrow) { v0 += rrow[n]; v1 += rrow[n + 1]; }
                if (Ch) {
                    *(__half2*)(Ch + (size_t)m * N + n) = __floats2half2_rn(v0, v1);
                } else {
                    *(float2*)(Cf + (size_t)m * N + n) = make_float2(v0, v1);
                }
            }
        }
    }
}

// ---------------- LayerNorm: fp32 in, fp16 or fp32 out ----------------
__global__ void __launch_bounds__(256) ln_kernel(
    const float* __restrict__ X, const float* __restrict__ w,
    const float* __restrict__ b, float* __restrict__ Yf, __half* __restrict__ Yh)
{
    const int t = blockIdx.x;
    const int tid = threadIdx.x;
    const float* xr = X + (size_t)t * DMODEL;
    float v0 = xr[tid], v1 = xr[tid + 256], v2 = xr[tid + 512];
    float s = v0 + v1 + v2;
    float s2 = v0 * v0 + v1 * v1 + v2 * v2;
#pragma unroll
    for (int o = 16; o > 0; o >>= 1) {
        s += __shfl_xor_sync(0xffffffffu, s, o);
        s2 += __shfl_xor_sync(0xffffffffu, s2, o);
    }
    __shared__ float rs[8], rs2[8];
    __shared__ float mS, rS;
    int wid = tid >> 5, lane = tid & 31;
    if (lane == 0) { rs[wid] = s; rs2[wid] = s2; }
    __syncthreads();
    if (tid == 0) {
        float S = 0.f, S2 = 0.f;
        for (int k = 0; k < 8; k++) { S += rs[k]; S2 += rs2[k]; }
        float m = S * (1.f / 768.f);
        float var = S2 * (1.f / 768.f) - m * m;
        mS = m;
        rS = rsqrtf(var + 1e-5f);
    }
    __syncthreads();
    float m = mS, r = rS;
    float o0 = (v0 - m) * r * w[tid] + b[tid];
    float o1 = (v1 - m) * r * w[tid + 256] + b[tid + 256];
    float o2 = (v2 - m) * r * w[tid + 512] + b[tid + 512];
    if (Yh) {
        __half* yr = Yh + (size_t)t * DMODEL;
        yr[tid] = __float2half_rn(o0);
        yr[tid + 256] = __float2half_rn(o1);
        yr[tid + 512] = __float2half_rn(o2);
    } else {
        float* yr = Yf + (size_t)t * DMODEL;
        yr[tid] = o0; yr[tid + 256] = o1; yr[tid + 512] = o2;
    }
}

// ---------------- fused attention, fp16 mma (m16n8k16) ----------------
#define KP    224
#define KSTRH 72     // halves
#define VSTRH 232    // halves
#define SSTRF 228    // floats
// layout (bytes): Ks 224*72*2=32256 | Vt 64*232*2=29696 | Qs 64*72*2=9216 | Ssf 64*228*4=58368 | Ps 64*232*2=29696
#define AT_KS   0
#define AT_VT   (AT_KS + KP * KSTRH * 2)
#define AT_QS   (AT_VT + 64 * VSTRH * 2)
#define AT_SSF  (AT_QS + 64 * KSTRH * 2)
#define AT_PS   (AT_SSF + 64 * SSTRF * 4)
#define ATTN_SMEM_BYTES (AT_PS + 64 * VSTRH * 2)   // 159232

__global__ void __launch_bounds__(256) attn_kernel(
    const __half* __restrict__ qkv, __half* __restrict__ O)
{
    extern __shared__ char smc[];
    __half* Ks  = (__half*)(smc + AT_KS);    // [224][72] key rows, d contiguous
    __half* Vt  = (__half*)(smc + AT_VT);    // [64][232] V transposed, key contiguous
    __half* Qs  = (__half*)(smc + AT_QS);    // [64][72]  Q tile, pre-scaled
    float*  Ssf = (float* )(smc + AT_SSF);   // [64][228] scores fp32
    __half* Ps  = (__half*)(smc + AT_PS);    // [64][232] probs fp16

    const int tid = threadIdx.x;
    const int b = blockIdx.x / NHEAD;
    const int h = blockIdx.x % NHEAD;
    const size_t base = (size_t)b * NSEQ * QKVDIM + h * 64;

    for (int idx = tid; idx < KP * 64; idx += 256) {
        int m = idx >> 6, d = idx & 63;
        __half kv = __float2half_rn(0.f), vv = kv;
        if (m < NSEQ) {
            kv = qkv[base + (size_t)m * QKVDIM + 768 + d];
            vv = qkv[base + (size_t)m * QKVDIM + 1536 + d];
        }
        Ks[m * KSTRH + d] = kv;
        Vt[d * VSTRH + m] = vv;
    }
    __syncthreads();

    const int wid = tid >> 5, lane = tid & 31;
    const int lr = lane >> 2, lc = lane & 3;
    const int wm = wid >> 2, wn = wid & 3;

    for (int q0 = 0; q0 < NSEQ; q0 += 64) {
        for (int idx = tid; idx < 64 * 64; idx += 256) {
            int i = idx >> 6, d = idx & 63;
            int r = q0 + i; if (r > NSEQ - 1) r = NSEQ - 1;
            Qs[i * KSTRH + d] = __float2half_rn(__half2float(qkv[base + (size_t)r * QKVDIM + d]) * 0.125f);
        }
        __syncthreads();

        // ---- S[64][224] = Q @ K^T : warp tile 32x56, K=64 (4 k-steps) ----
        {
            float acc[2][7][4];
#pragma unroll
            for (int mi = 0; mi < 2; mi++)
#pragma unroll
                for (int ni = 0; ni < 7; ni++)
#pragma unroll
                    for (int q = 0; q < 4; q++) acc[mi][ni][q] = 0.f;
#pragma unroll
            for (int kk = 0; kk < 4; kk++) {
                const int koff = (kk << 4) + (lc << 1);
                unsigned af[2][4], bf[7][2];
#pragma unroll
                for (int mi = 0; mi < 2; mi++) {
                    const __half* ap = Qs + (wm * 32 + mi * 16 + lr) * KSTRH + koff;
                    af[mi][0] = *(const unsigned*)(ap);
                    af[mi][1] = *(const unsigned*)(ap + 8 * KSTRH);
                    af[mi][2] = *(const unsigned*)(ap + 8);
                    af[mi][3] = *(const unsigned*)(ap + 8 * KSTRH + 8);
                }
#pragma unroll
                for (int ni = 0; ni < 7; ni++) {
                    const __half* bp = Ks + (wn * 56 + ni * 8 + lr) * KSTRH + koff;
                    bf[ni][0] = *(const unsigned*)(bp);
                    bf[ni][1] = *(const unsigned*)(bp + 8);
                }
#pragma unroll
                for (int mi = 0; mi < 2; mi++)
#pragma unroll
                    for (int ni = 0; ni < 7; ni++)
                        mma_f16(acc[mi][ni], af[mi], bf[ni]);
            }
#pragma unroll
            for (int mi = 0; mi < 2; mi++) {
                const int r0 = wm * 32 + mi * 16 + lr;
#pragma unroll
                for (int ni = 0; ni < 7; ni++) {
                    const int c0 = wn * 56 + ni * 8 + 2 * lc;
                    Ssf[r0 * SSTRF + c0]           = acc[mi][ni][0];
                    Ssf[r0 * SSTRF + c0 + 1]       = acc[mi][ni][1];
                    Ssf[(r0 + 8) * SSTRF + c0]     = acc[mi][ni][2];
                    Ssf[(r0 + 8) * SSTRF + c0 + 1] = acc[mi][ni][3];
                }
            }
        }
        __syncthreads();

        // ---- softmax (fp32) -> Ps (fp16), zero pads ----
        for (int row = wid; row < 64; row += 8) {
            const float* srow = Ssf + row * SSTRF;
            __half* prow = Ps + row * VSTRH;
            float mx = -1e30f;
            for (int m = lane; m < NSEQ; m += 32) mx = fmaxf(mx, srow[m]);
#pragma unroll
            for (int o = 16; o > 0; o >>= 1) mx = fmaxf(mx, __shfl_xor_sync(0xffffffffu, mx, o));
            float sum = 0.f;
            float ebuf[7];
            for (int m = lane, q = 0; m < NSEQ; m += 32, q++) {
                float e = expf(srow[m] - mx);
                ebuf[q] = e;
                sum += e;
            }
#pragma unroll
            for (int o = 16; o > 0; o >>= 1) sum += __shfl_xor_sync(0xffffffffu, sum, o);
            float inv = 1.f / sum;
            for (int m = lane, q = 0; m < NSEQ; m += 32, q++)
                prow[m] = __float2half_rn(ebuf[q] * inv);
            if (lane < KP - NSEQ) prow[NSEQ + lane] = __float2half_rn(0.f);
        }
        __syncthreads();

        // ---- O[64][64] = P @ V : warp tile 32x16, K=224 (14 k-steps) ----
        {
            float acc2[2][2][4];
#pragma unroll
            for (int mi = 0; mi < 2; mi++)
#pragma unroll
                for (int ni = 0; ni < 2; ni++)
#pragma unroll
                    for (int q = 0; q < 4; q++) acc2[mi][ni][q] = 0.f;
#pragma unroll
            for (int kk = 0; kk < 14; kk++) {
                const int koff = (kk << 4) + (lc << 1);
                unsigned af[2][4], bf[2][2];
#pragma unroll
                for (int mi = 0; mi < 2; mi++) {
                    const __half* ap = Ps + (wm * 32 + mi * 16 + lr) * VSTRH + koff;
                    af[mi][0] = *(const unsigned*)(ap);
                    af[mi][1] = *(const unsigned*)(ap + 8 * VSTRH);
                    af[mi][2] = *(const unsigned*)(ap + 8);
                    af[mi][3] = *(const unsigned*)(ap + 8 * VSTRH + 8);
                }
#pragma unroll
                for (int ni = 0; ni < 2; ni++) {
                    const __half* bp = Vt + (wn * 16 + ni * 8 + lr) * VSTRH + koff;
                    bf[ni][0] = *(const unsigned*)(bp);
                    bf[ni][1] = *(const unsigned*)(bp + 8);
                }
#pragma unroll
                for (int mi = 0; mi < 2; mi++)
#pragma unroll
                    for (int ni = 0; ni < 2; ni++)
                        mma_f16(acc2[mi][ni], af[mi], bf[ni]);
            }
#pragma unroll
            for (int mi = 0; mi < 2; mi++) {
#pragma unroll
                for (int half_ = 0; half_ < 2; half_++) {
                    const int r = q0 + wm * 32 + mi * 16 + lr + half_ * 8;
                    if (r < NSEQ) {
                        __half* orow = O + (size_t)(b * NSEQ + r) * DMODEL + h * 64;
#pragma unroll
                        for (int ni = 0; ni < 2; ni++) {
                            const int n = wn * 16 + ni * 8 + 2 * lc;
                            *(__half2*)(orow + n) =
                                __floats2half2_rn(acc2[mi][ni][half_ * 2 + 0], acc2[mi][ni][half_ * 2 + 1]);
                        }
                    }
                }
            }
        }
        __syncthreads();
    }
}

// ---------------- launch ----------------
extern "C" void kernel_launch(void* const* d_in, const int* in_sizes, int n_in,
                              void* d_out, int out_size)
{
    const float* x       = (const float*)d_in[0];
    const float* patch_w = (const float*)d_in[1];
    const float* patch_b = (const float*)d_in[2];
    const float* pos     = (const float*)d_in[3];
    const float* ln1_w   = (const float*)d_in[4];
    const float* ln1_b   = (const float*)d_in[5];
    const float* qkv_w   = (const float*)d_in[6];
    const float* qkv_b   = (const float*)d_in[7];
    const float* proj_w  = (const float*)d_in[8];
    const float* proj_b  = (const float*)d_in[9];
    const float* ln2_w   = (const float*)d_in[10];
    const float* ln2_b   = (const float*)d_in[11];
    const float* fc1_w   = (const float*)d_in[12];
    const float* fc1_b   = (const float*)d_in[13];
    const float* fc2_w   = (const float*)d_in[14];
    const float* fc2_b   = (const float*)d_in[15];
    const float* lnf_w   = (const float*)d_in[16];
    const float* lnf_b   = (const float*)d_in[17];

    float *h; __half *y, *qkv, *o, *ff, *im, *w;
    cudaGetSymbolAddress((void**)&h,   g_h);
    cudaGetSymbolAddress((void**)&y,   g_y);
    cudaGetSymbolAddress((void**)&qkv, g_qkv);
    cudaGetSymbolAddress((void**)&o,   g_o);
    cudaGetSymbolAddress((void**)&ff,  g_ff);
    cudaGetSymbolAddress((void**)&im,  g_im);
    cudaGetSymbolAddress((void**)&w,   g_w);

    cudaFuncSetAttribute(attn_kernel, cudaFuncAttributeMaxDynamicSharedMemorySize, ATTN_SMEM_BYTES);
    cudaFuncSetAttribute(gemm_mma, cudaFuncAttributeMaxDynamicSharedMemorySize, GSMEM);

    // order: profiled launch index 3 = patch-embed gemm_mma
    cvt_kernel<<<(  589824/4 + 255)/256, 256>>>((const float4*)patch_w,(__half2*)(w + OPATCH),   589824/4); // 0
    im2col_kernel<<<(NTOK * DMODEL + 255) / 256, 256>>>(x, im);                                             // 1
    cvt_kernel<<<(21233664/4 + 255)/256, 256>>>((const float4*)qkv_w,  (__half2*)(w + OQKV),   21233664/4); // 2
    gemm_mma<<<dim3(DMODEL / 128, NTOK / 128), 256, GSMEM>>>(                                               // 3 <- profiled
        im, w + OPATCH, patch_b, nullptr, pos, h, nullptr, DMODEL, DMODEL, 0);
    cvt_kernel<<<( 7077888/4 + 255)/256, 256>>>((const float4*)proj_w, (__half2*)(w + OPROJ),   7077888/4); // 4
    cvt_kernel<<<(28311552/4 + 255)/256, 256>>>((const float4*)fc1_w,  (__half2*)(w + OFC1),   28311552/4); // 5
    cvt_kernel<<<(28311552/4 + 255)/256, 256>>>((const float4*)fc2_w,  (__half2*)(w + OFC2),   28311552/4); // 6

    for (int l = 0; l < NLAYER; l++) {
        ln_kernel<<<NTOK, 256>>>(h, ln1_w + l * DMODEL, ln1_b + l * DMODEL, nullptr, y);
        gemm_mma<<<dim3(QKVDIM / 128, NTOK / 128), 256, GSMEM>>>(
            y, w + OQKV + (size_t)l * QKVDIM * DMODEL, qkv_b + l * QKVDIM,
            nullptr, nullptr, nullptr, qkv, QKVDIM, DMODEL, 0);
        attn_kernel<<<32 * NHEAD, 256, ATTN_SMEM_BYTES>>>(qkv, o);
        gemm_mma<<<dim3(DMODEL / 128, NTOK / 128), 256, GSMEM>>>(
            o, w + OPROJ + (size_t)l * DMODEL * DMODEL, proj_b + l * DMODEL,
            h, nullptr, h, nullptr, DMODEL, DMODEL, 0);
        ln_kernel<<<NTOK, 256>>>(h, ln2_w + l * DMODEL, ln2_b + l * DMODEL, nullptr, y);
        gemm_mma<<<dim3(FFDIM / 128, NTOK / 128), 256, GSMEM>>>(
            y, w + OFC1 + (size_t)l * FFDIM * DMODEL, fc1_b + l * FFDIM,
            nullptr, nullptr, nullptr, ff, FFDIM, DMODEL, 1);
        gemm_mma<<<dim3(DMODEL / 128, NTOK / 128), 256, GSMEM>>>(
            ff, w + OFC2 + (size_t)l * DMODEL * FFDIM, fc2_b + l * DMODEL,
            h, nullptr, h, nullptr, DMODEL, FFDIM, 0);
    }
    ln_kernel<<<NTOK, 256>>>(h, lnf_w, lnf_b, (float*)d_out, nullptr);
}

// round 8
// speedup vs baseline: 4.9924x; 1.0631x over previous
#include <cuda_runtime.h>
#include <cuda_fp16.h>
#include <math.h>

// ---------------- problem constants ----------------
#define NTOK   6272
#define DMODEL 768
#define FFDIM  3072
#define QKVDIM 2304
#define NHEAD  12
#define NSEQ   196
#define NLAYER 12

// ---------------- weight scratch offsets (half elements) ----------------
#define OQKV   0
#define OPROJ  21233664
#define OFC1   28311552
#define OFC2   56623104
#define OPATCH 84934656
#define WTOTAL 85524480

__device__ __align__(256) __half g_w  [WTOTAL];
__device__ __align__(256) float  g_h  [NTOK * DMODEL];   // residual stream fp32
__device__ __align__(256) __half g_y  [NTOK * DMODEL];
__device__ __align__(256) __half g_qkv[NTOK * QKVDIM];
__device__ __align__(256) __half g_o  [NTOK * DMODEL];
__device__ __align__(256) __half g_ff [NTOK * FFDIM];
__device__ __align__(256) __half g_im [NTOK * DMODEL];

// ---------------- helpers ----------------
__device__ __forceinline__ void mma_f16(float* c, const unsigned* a, const unsigned* b) {
    asm volatile("mma.sync.aligned.m16n8k16.row.col.f32.f16.f16.f32 "
        "{%0,%1,%2,%3}, {%4,%5,%6,%7}, {%8,%9}, {%0,%1,%2,%3};"
        : "+f"(c[0]), "+f"(c[1]), "+f"(c[2]), "+f"(c[3])
        : "r"(a[0]), "r"(a[1]), "r"(a[2]), "r"(a[3]), "r"(b[0]), "r"(b[1]));
}
__device__ __forceinline__ void ldm_x4(unsigned& r0, unsigned& r1, unsigned& r2, unsigned& r3,
                                       unsigned addr) {
    asm volatile("ldmatrix.sync.aligned.m8n8.x4.shared.b16 {%0,%1,%2,%3}, [%4];"
        : "=r"(r0), "=r"(r1), "=r"(r2), "=r"(r3) : "r"(addr));
}

// ---------------- weight f32 -> f16 pass ----------------
__global__ void cvt_kernel(const float4* __restrict__ s, __half2* __restrict__ d, int n4) {
    int i = blockIdx.x * 256 + threadIdx.x;
    if (i >= n4) return;
    float4 v = s[i];
    d[2 * i]     = __floats2half2_rn(v.x, v.y);
    d[2 * i + 1] = __floats2half2_rn(v.z, v.w);
}

// ---------------- im2col -> f16 ----------------
__global__ void im2col_kernel(const float* __restrict__ x, __half* __restrict__ out) {
    int idx = blockIdx.x * 256 + threadIdx.x;
    if (idx >= NTOK * DMODEL) return;
    int t = idx / 768, r = idx % 768;
    int c = r >> 8;
    int ij = r & 255;
    int i = ij >> 4, j = ij & 15;
    int b = t / 196, p = t % 196;
    int py = p / 14, px = p % 14;
    out[idx] = __float2half_rn(x[((size_t)(b * 3 + c) * 224 + py * 16 + i) * 224 + px * 16 + j]);
}

// ---------------- fp16 mma GEMM: C[M,N] = A[M,K] @ W[N,K]^T (+epilogue) ----------------
// 128x128x32 tile, 256 threads (8 warps 2x4), warp tile 64x32.
// 4-stage cp.async ring, ONE __syncthreads per chunk, ldmatrix fragments, 2 CTAs/SM.
#define TPADH  40                      // halves; 80B rows; ldmatrix rows stride 20 banks (conflict-free)
#define TILEH  (128 * TPADH)
#define STAGEH (2 * TILEH)
#define GSMEM  (4 * STAGEH * 2)        // 81920 bytes

__device__ __forceinline__ void load_tile_pair(unsigned sdst, const __half* __restrict__ Ab,
                                               const __half* __restrict__ Wb, int K, int k0, int tid)
{
#pragma unroll
    for (int half_ = 0; half_ < 2; half_++) {
        const __half* src = (half_ ? Wb : Ab) + k0;
        unsigned base = sdst + half_ * (TILEH * 2);
#pragma unroll
        for (int j = 0; j < 2; j++) {
            int i = (j << 8) + tid;            // 0..511 16B segments
            int row = i >> 2, c16 = i & 3;
            unsigned d = base + (row * TPADH + (c16 << 3)) * 2;
            const __half* s = src + (size_t)row * K + (c16 << 3);
            asm volatile("cp.async.cg.shared.global [%0], [%1], 16;" :: "r"(d), "l"(s));
        }
    }
}

__global__ void __launch_bounds__(256, 2) gemm_mma(
    const __half* __restrict__ A, const __half* __restrict__ W,
    const float* __restrict__ bias, const float* __restrict__ res,
    const float* __restrict__ pos, float* __restrict__ Cf,
    __half* __restrict__ Ch, int N, int K, int act)
{
    extern __shared__ __half smh[];
    const int tid = threadIdx.x;
    const int bm = blockIdx.y << 7, bn = blockIdx.x << 7;
    const int wid = tid >> 5, lane = tid & 31;
    const int wm = wid >> 2, wn = wid & 3;
    const int lr = lane >> 2, lc = lane & 3;
    unsigned sbase;
    asm("{ .reg .u64 t; cvta.to.shared.u64 t, %1; cvt.u32.u64 %0, t; }" : "=r"(sbase) : "l"(smh));

    const __half* Ab = A + (size_t)bm * K;
    const __half* Wb = W + (size_t)bn * K;
    const int NC = K >> 5;

    // ldmatrix per-lane base offsets (bytes within a stage)
    // A x4: mat0=(r0-7,k0-7), mat1=(r8-15,k0-7), mat2=(r0-7,k8-15), mat3=(r8-15,k8-15)
    unsigned a_off[4];
#pragma unroll
    for (int mi = 0; mi < 4; mi++) {
        int row = wm * 64 + mi * 16 + (lane & 7) + (((lane >> 3) & 1) << 3);
        a_off[mi] = sbase + ((unsigned)(row * TPADH + ((lane >> 4) << 3)) << 1);
    }
    // B x4 (two n-groups): mat0=(nj,k0-7), mat1=(nj,k8-15), mat2=(nj+8,k0-7), mat3=(nj+8,k8-15)
    unsigned b_off[2];
#pragma unroll
    for (int nj = 0; nj < 2; nj++) {
        int row = wn * 32 + nj * 16 + ((lane >> 4) << 3) + (lane & 7);
        b_off[nj] = sbase + TILEH * 2 +
                    ((unsigned)(row * TPADH + (((lane >> 3) & 1) << 3)) << 1);
    }

    float acc[4][4][4];
#pragma unroll
    for (int mi = 0; mi < 4; mi++)
#pragma unroll
        for (int ni = 0; ni < 4; ni++)
#pragma unroll
            for (int q = 0; q < 4; q++) acc[mi][ni][q] = 0.f;

    // prologue: stages 0,1,2
    load_tile_pair(sbase,                Ab, Wb, K, 0,  tid);
    asm volatile("cp.async.commit_group;" ::: "memory");
    load_tile_pair(sbase + STAGEH * 2,   Ab, Wb, K, 32, tid);
    asm volatile("cp.async.commit_group;" ::: "memory");
    load_tile_pair(sbase + STAGEH * 4,   Ab, Wb, K, 64, tid);
    asm volatile("cp.async.commit_group;" ::: "memory");

    for (int c = 0; c < NC; c++) {
        asm volatile("cp.async.wait_group 2;" ::: "memory");   // chunk c resident
        __syncthreads();   // all warps done reading slot (c)%4's previous contents & chunk c visible

        if (c + 3 < NC)
            load_tile_pair(sbase + ((c + 3) & 3) * (STAGEH * 2), Ab, Wb, K, (c + 3) << 5, tid);
        asm volatile("cp.async.commit_group;" ::: "memory");

        const unsigned soff = (unsigned)((c & 3) * (STAGEH * 2));
#pragma unroll
        for (int kk = 0; kk < 2; kk++) {
            const unsigned koff = soff + (kk << 5);
            unsigned af[4][4], bf[4][2];
#pragma unroll
            for (int mi = 0; mi < 4; mi++)
                ldm_x4(af[mi][0], af[mi][1], af[mi][2], af[mi][3], a_off[mi] + koff);
#pragma unroll
            for (int nj = 0; nj < 2; nj++)
                ldm_x4(bf[2 * nj][0], bf[2 * nj][1], bf[2 * nj + 1][0], bf[2 * nj + 1][1],
                       b_off[nj] + koff);
#pragma unroll
            for (int mi = 0; mi < 4; mi++)
#pragma unroll
                for (int ni = 0; ni < 4; ni++)
                    mma_f16(acc[mi][ni], af[mi], bf[ni]);
        }
    }

    // ---- epilogue: fp32 math, output fp32 (Cf) or fp16 (Ch) ----
#pragma unroll
    for (int mi = 0; mi < 4; mi++) {
#pragma unroll
        for (int half_ = 0; half_ < 2; half_++) {
            const int m = bm + wm * 64 + mi * 16 + lr + half_ * 8;
            const float* rrow = res ? res + (size_t)m * N : nullptr;
            const float* prow = pos ? pos + (size_t)(m % NSEQ) * N : nullptr;
#pragma unroll
            for (int ni = 0; ni < 4; ni++) {
                const int n = bn + wn * 32 + ni * 8 + 2 * lc;
                float v0 = acc[mi][ni][half_ * 2 + 0];
                float v1 = acc[mi][ni][half_ * 2 + 1];
                v0 += bias[n]; v1 += bias[n + 1];
                if (act) {
                    v0 = 0.5f * v0 * (1.f + erff(v0 * 0.70710678118654752f));
                    v1 = 0.5f * v1 * (1.f + erff(v1 * 0.70710678118654752f));
                }
                if (prow) { v0 += prow[n]; v1 += prow[n + 1]; }
                if (rrow) { v0 += rrow[n]; v1 += rrow[n + 1]; }
                if (Ch) {
                    *(__half2*)(Ch + (size_t)m * N + n) = __floats2half2_rn(v0, v1);
                } else {
                    *(float2*)(Cf + (size_t)m * N + n) = make_float2(v0, v1);
                }
            }
        }
    }
}

// ---------------- LayerNorm: fp32 in, fp16 or fp32 out ----------------
__global__ void __launch_bounds__(256) ln_kernel(
    const float* __restrict__ X, const float* __restrict__ w,
    const float* __restrict__ b, float* __restrict__ Yf, __half* __restrict__ Yh)
{
    const int t = blockIdx.x;
    const int tid = threadIdx.x;
    const float* xr = X + (size_t)t * DMODEL;
    float v0 = xr[tid], v1 = xr[tid + 256], v2 = xr[tid + 512];
    float s = v0 + v1 + v2;
    float s2 = v0 * v0 + v1 * v1 + v2 * v2;
#pragma unroll
    for (int o = 16; o > 0; o >>= 1) {
        s += __shfl_xor_sync(0xffffffffu, s, o);
        s2 += __shfl_xor_sync(0xffffffffu, s2, o);
    }
    __shared__ float rs[8], rs2[8];
    __shared__ float mS, rS;
    int wid = tid >> 5, lane = tid & 31;
    if (lane == 0) { rs[wid] = s; rs2[wid] = s2; }
    __syncthreads();
    if (tid == 0) {
        float S = 0.f, S2 = 0.f;
        for (int k = 0; k < 8; k++) { S += rs[k]; S2 += rs2[k]; }
        float m = S * (1.f / 768.f);
        float var = S2 * (1.f / 768.f) - m * m;
        mS = m;
        rS = rsqrtf(var + 1e-5f);
    }
    __syncthreads();
    float m = mS, r = rS;
    float o0 = (v0 - m) * r * w[tid] + b[tid];
    float o1 = (v1 - m) * r * w[tid + 256] + b[tid + 256];
    float o2 = (v2 - m) * r * w[tid + 512] + b[tid + 512];
    if (Yh) {
        __half* yr = Yh + (size_t)t * DMODEL;
        yr[tid] = __float2half_rn(o0);
        yr[tid + 256] = __float2half_rn(o1);
        yr[tid + 512] = __float2half_rn(o2);
    } else {
        float* yr = Yf + (size_t)t * DMODEL;
        yr[tid] = o0; yr[tid + 256] = o1; yr[tid + 512] = o2;
    }
}

// ---------------- fused attention, fp16 mma (m16n8k16) ----------------
#define KP    224
#define KSTRH 72     // halves
#define VSTRH 232    // halves
#define SSTRF 228    // floats
#define AT_KS   0
#define AT_VT   (AT_KS + KP * KSTRH * 2)
#define AT_QS   (AT_VT + 64 * VSTRH * 2)
#define AT_SSF  (AT_QS + 64 * KSTRH * 2)
#define AT_PS   (AT_SSF + 64 * SSTRF * 4)
#define ATTN_SMEM_BYTES (AT_PS + 64 * VSTRH * 2)   // 159232

__global__ void __launch_bounds__(256) attn_kernel(
    const __half* __restrict__ qkv, __half* __restrict__ O)
{
    extern __shared__ char smc[];
    __half* Ks  = (__half*)(smc + AT_KS);
    __half* Vt  = (__half*)(smc + AT_VT);
    __half* Qs  = (__half*)(smc + AT_QS);
    float*  Ssf = (float* )(smc + AT_SSF);
    __half* Ps  = (__half*)(smc + AT_PS);

    const int tid = threadIdx.x;
    const int b = blockIdx.x / NHEAD;
    const int h = blockIdx.x % NHEAD;
    const size_t base = (size_t)b * NSEQ * QKVDIM + h * 64;

    for (int idx = tid; idx < KP * 64; idx += 256) {
        int m = idx >> 6, d = idx & 63;
        __half kv = __float2half_rn(0.f), vv = kv;
        if (m < NSEQ) {
            kv = qkv[base + (size_t)m * QKVDIM + 768 + d];
            vv = qkv[base + (size_t)m * QKVDIM + 1536 + d];
        }
        Ks[m * KSTRH + d] = kv;
        Vt[d * VSTRH + m] = vv;
    }
    __syncthreads();

    const int wid = tid >> 5, lane = tid & 31;
    const int lr = lane >> 2, lc = lane & 3;
    const int wm = wid >> 2, wn = wid & 3;

    for (int q0 = 0; q0 < NSEQ; q0 += 64) {
        for (int idx = tid; idx < 64 * 64; idx += 256) {
            int i = idx >> 6, d = idx & 63;
            int r = q0 + i; if (r > NSEQ - 1) r = NSEQ - 1;
            Qs[i * KSTRH + d] = __float2half_rn(__half2float(qkv[base + (size_t)r * QKVDIM + d]) * 0.125f);
        }
        __syncthreads();

        // ---- S[64][224] = Q @ K^T : warp tile 32x56, K=64 ----
        {
            float acc[2][7][4];
#pragma unroll
            for (int mi = 0; mi < 2; mi++)
#pragma unroll
                for (int ni = 0; ni < 7; ni++)
#pragma unroll
                    for (int q = 0; q < 4; q++) acc[mi][ni][q] = 0.f;
#pragma unroll
            for (int kk = 0; kk < 4; kk++) {
                const int koff = (kk << 4) + (lc << 1);
                unsigned af[2][4], bf[7][2];
#pragma unroll
                for (int mi = 0; mi < 2; mi++) {
                    const __half* ap = Qs + (wm * 32 + mi * 16 + lr) * KSTRH + koff;
                    af[mi][0] = *(const unsigned*)(ap);
                    af[mi][1] = *(const unsigned*)(ap + 8 * KSTRH);
                    af[mi][2] = *(const unsigned*)(ap + 8);
                    af[mi][3] = *(const unsigned*)(ap + 8 * KSTRH + 8);
                }
#pragma unroll
                for (int ni = 0; ni < 7; ni++) {
                    const __half* bp = Ks + (wn * 56 + ni * 8 + lr) * KSTRH + koff;
                    bf[ni][0] = *(const unsigned*)(bp);
                    bf[ni][1] = *(const unsigned*)(bp + 8);
                }
#pragma unroll
                for (int mi = 0; mi < 2; mi++)
#pragma unroll
                    for (int ni = 0; ni < 7; ni++)
                        mma_f16(acc[mi][ni], af[mi], bf[ni]);
            }
#pragma unroll
            for (int mi = 0; mi < 2; mi++) {
                const int r0 = wm * 32 + mi * 16 + lr;
#pragma unroll
                for (int ni = 0; ni < 7; ni++) {
                    const int c0 = wn * 56 + ni * 8 + 2 * lc;
                    Ssf[r0 * SSTRF + c0]           = acc[mi][ni][0];
                    Ssf[r0 * SSTRF + c0 + 1]       = acc[mi][ni][1];
                    Ssf[(r0 + 8) * SSTRF + c0]     = acc[mi][ni][2];
                    Ssf[(r0 + 8) * SSTRF + c0 + 1] = acc[mi][ni][3];
                }
            }
        }
        __syncthreads();

        // ---- softmax (fp32) -> Ps (fp16), zero pads ----
        for (int row = wid; row < 64; row += 8) {
            const float* srow = Ssf + row * SSTRF;
            __half* prow = Ps + row * VSTRH;
            float mx = -1e30f;
            for (int m = lane; m < NSEQ; m += 32) mx = fmaxf(mx, srow[m]);
#pragma unroll
            for (int o = 16; o > 0; o >>= 1) mx = fmaxf(mx, __shfl_xor_sync(0xffffffffu, mx, o));
            float sum = 0.f;
            float ebuf[7];
            for (int m = lane, q = 0; m < NSEQ; m += 32, q++) {
                float e = expf(srow[m] - mx);
                ebuf[q] = e;
                sum += e;
            }
#pragma unroll
            for (int o = 16; o > 0; o >>= 1) sum += __shfl_xor_sync(0xffffffffu, sum, o);
            float inv = 1.f / sum;
            for (int m = lane, q = 0; m < NSEQ; m += 32, q++)
                prow[m] = __float2half_rn(ebuf[q] * inv);
            if (lane < KP - NSEQ) prow[NSEQ + lane] = __float2half_rn(0.f);
        }
        __syncthreads();

        // ---- O[64][64] = P @ V : warp tile 32x16, K=224 ----
        {
            float acc2[2][2][4];
#pragma unroll
            for (int mi = 0; mi < 2; mi++)
#pragma unroll
                for (int ni = 0; ni < 2; ni++)
#pragma unroll
                    for (int q = 0; q < 4; q++) acc2[mi][ni][q] = 0.f;
#pragma unroll
            for (int kk = 0; kk < 14; kk++) {
                const int koff = (kk << 4) + (lc << 1);
                unsigned af[2][4], bf[2][2];
#pragma unroll
                for (int mi = 0; mi < 2; mi++) {
                    const __half* ap = Ps + (wm * 32 + mi * 16 + lr) * VSTRH + koff;
                    af[mi][0] = *(const unsigned*)(ap);
                    af[mi][1] = *(const unsigned*)(ap + 8 * VSTRH);
                    af[mi][2] = *(const unsigned*)(ap + 8);
                    af[mi][3] = *(const unsigned*)(ap + 8 * VSTRH + 8);
                }
#pragma unroll
                for (int ni = 0; ni < 2; ni++) {
                    const __half* bp = Vt + (wn * 16 + ni * 8 + lr) * VSTRH + koff;
                    bf[ni][0] = *(const unsigned*)(bp);
                    bf[ni][1] = *(const unsigned*)(bp + 8);
                }
#pragma unroll
                for (int mi = 0; mi < 2; mi++)
#pragma unroll
                    for (int ni = 0; ni < 2; ni++)
                        mma_f16(acc2[mi][ni], af[mi], bf[ni]);
            }
#pragma unroll
            for (int mi = 0; mi < 2; mi++) {
#pragma unroll
                for (int half_ = 0; half_ < 2; half_++) {
                    const int r = q0 + wm * 32 + mi * 16 + lr + half_ * 8;
                    if (r < NSEQ) {
                        __half* orow = O + (size_t)(b * NSEQ + r) * DMODEL + h * 64;
#pragma unroll
                        for (int ni = 0; ni < 2; ni++) {
                            const int n = wn * 16 + ni * 8 + 2 * lc;
                            *(__half2*)(orow + n) =
                                __floats2half2_rn(acc2[mi][ni][half_ * 2 + 0], acc2[mi][ni][half_ * 2 + 1]);
                        }
                    }
                }
            }
        }
        __syncthreads();
    }
}

// ---------------- launch ----------------
extern "C" void kernel_launch(void* const* d_in, const int* in_sizes, int n_in,
                              void* d_out, int out_size)
{
    const float* x       = (const float*)d_in[0];
    const float* patch_w = (const float*)d_in[1];
    const float* patch_b = (const float*)d_in[2];
    const float* pos     = (const float*)d_in[3];
    const float* ln1_w   = (const float*)d_in[4];
    const float* ln1_b   = (const float*)d_in[5];
    const float* qkv_w   = (const float*)d_in[6];
    const float* qkv_b   = (const float*)d_in[7];
    const float* proj_w  = (const float*)d_in[8];
    const float* proj_b  = (const float*)d_in[9];
    const float* ln2_w   = (const float*)d_in[10];
    const float* ln2_b   = (const float*)d_in[11];
    const float* fc1_w   = (const float*)d_in[12];
    const float* fc1_b   = (const float*)d_in[13];
    const float* fc2_w   = (const float*)d_in[14];
    const float* fc2_b   = (const float*)d_in[15];
    const float* lnf_w   = (const float*)d_in[16];
    const float* lnf_b   = (const float*)d_in[17];

    float *h; __half *y, *qkv, *o, *ff, *im, *w;
    cudaGetSymbolAddress((void**)&h,   g_h);
    cudaGetSymbolAddress((void**)&y,   g_y);
    cudaGetSymbolAddress((void**)&qkv, g_qkv);
    cudaGetSymbolAddress((void**)&o,   g_o);
    cudaGetSymbolAddress((void**)&ff,  g_ff);
    cudaGetSymbolAddress((void**)&im,  g_im);
    cudaGetSymbolAddress((void**)&w,   g_w);

    cudaFuncSetAttribute(attn_kernel, cudaFuncAttributeMaxDynamicSharedMemorySize, ATTN_SMEM_BYTES);
    cudaFuncSetAttribute(gemm_mma, cudaFuncAttributeMaxDynamicSharedMemorySize, GSMEM);

    // order: profiled launch index 3 = patch-embed gemm_mma
    cvt_kernel<<<(  589824/4 + 255)/256, 256>>>((const float4*)patch_w,(__half2*)(w + OPATCH),   589824/4); // 0
    im2col_kernel<<<(NTOK * DMODEL + 255) / 256, 256>>>(x, im);                                             // 1
    cvt_kernel<<<(21233664/4 + 255)/256, 256>>>((const float4*)qkv_w,  (__half2*)(w + OQKV),   21233664/4); // 2
    gemm_mma<<<dim3(DMODEL / 128, NTOK / 128), 256, GSMEM>>>(                                               // 3 <- profiled
        im, w + OPATCH, patch_b, nullptr, pos, h, nullptr, DMODEL, DMODEL, 0);
    cvt_kernel<<<( 7077888/4 + 255)/256, 256>>>((const float4*)proj_w, (__half2*)(w + OPROJ),   7077888/4); // 4
    cvt_kernel<<<(28311552/4 + 255)/256, 256>>>((const float4*)fc1_w,  (__half2*)(w + OFC1),   28311552/4); // 5
    cvt_kernel<<<(28311552/4 + 255)/256, 256>>>((const float4*)fc2_w,  (__half2*)(w + OFC2),   28311552/4); // 6

    for (int l = 0; l < NLAYER; l++) {
        ln_kernel<<<NTOK, 256>>>(h, ln1_w + l * DMODEL, ln1_b + l * DMODEL, nullptr, y);
        gemm_mma<<<dim3(QKVDIM / 128, NTOK / 128), 256, GSMEM>>>(
            y, w + OQKV + (size_t)l * QKVDIM * DMODEL, qkv_b + l * QKVDIM,
            nullptr, nullptr, nullptr, qkv, QKVDIM, DMODEL, 0);
        attn_kernel<<<32 * NHEAD, 256, ATTN_SMEM_BYTES>>>(qkv, o);
        gemm_mma<<<dim3(DMODEL / 128, NTOK / 128), 256, GSMEM>>>(
            o, w + OPROJ + (size_t)l * DMODEL * DMODEL, proj_b + l * DMODEL,
            h, nullptr, h, nullptr, DMODEL, DMODEL, 0);
        ln_kernel<<<NTOK, 256>>>(h, ln2_w + l * DMODEL, ln2_b + l * DMODEL, nullptr, y);
        gemm_mma<<<dim3(FFDIM / 128, NTOK / 128), 256, GSMEM>>>(
            y, w + OFC1 + (size_t)l * FFDIM * DMODEL, fc1_b + l * FFDIM,
            nullptr, nullptr, nullptr, ff, FFDIM, DMODEL, 1);
        gemm_mma<<<dim3(DMODEL / 128, NTOK / 128), 256, GSMEM>>>(
            ff, w + OFC2 + (size_t)l * DMODEL * FFDIM, fc2_b + l * DMODEL,
            h, nullptr, h, nullptr, DMODEL, FFDIM, 0);
    }
    ln_kernel<<<NTOK, 256>>>(h, lnf_w, lnf_b, (float*)d_out, nullptr);
}

// round 9
// speedup vs baseline: 5.3863x; 1.0789x over previous
#include <cuda_runtime.h>
#include <cuda_fp16.h>
#include <math.h>

// ---------------- problem constants ----------------
#define NTOK   6272
#define DMODEL 768
#define FFDIM  3072
#define QKVDIM 2304
#define NHEAD  12
#define NSEQ   196
#define NLAYER 12

// ---------------- weight scratch offsets (half elements) ----------------
#define OQKV   0
#define OPROJ  21233664
#define OFC1   28311552
#define OFC2   56623104
#define OPATCH 84934656
#define WTOTAL 85524480

__device__ __align__(256) __half g_w  [WTOTAL];
__device__ __align__(256) float  g_h  [NTOK * DMODEL];   // residual stream fp32
__device__ __align__(256) __half g_y  [NTOK * DMODEL];
__device__ __align__(256) __half g_qkv[NTOK * QKVDIM];
__device__ __align__(256) __half g_o  [NTOK * DMODEL];
__device__ __align__(256) __half g_ff [NTOK * FFDIM];
__device__ __align__(256) __half g_im [NTOK * DMODEL];

// ---------------- helpers ----------------
__device__ __forceinline__ void mma_f16(float* c, const unsigned* a, const unsigned* b) {
    asm volatile("mma.sync.aligned.m16n8k16.row.col.f32.f16.f16.f32 "
        "{%0,%1,%2,%3}, {%4,%5,%6,%7}, {%8,%9}, {%0,%1,%2,%3};"
        : "+f"(c[0]), "+f"(c[1]), "+f"(c[2]), "+f"(c[3])
        : "r"(a[0]), "r"(a[1]), "r"(a[2]), "r"(a[3]), "r"(b[0]), "r"(b[1]));
}
__device__ __forceinline__ void ldm_x4(unsigned& r0, unsigned& r1, unsigned& r2, unsigned& r3,
                                       unsigned addr) {
    asm volatile("ldmatrix.sync.aligned.m8n8.x4.shared.b16 {%0,%1,%2,%3}, [%4];"
        : "=r"(r0), "=r"(r1), "=r"(r2), "=r"(r3) : "r"(addr));
}

// ---------------- weight f32 -> f16 pass ----------------
__global__ void cvt_kernel(const float4* __restrict__ s, __half2* __restrict__ d, int n4) {
    int i = blockIdx.x * 256 + threadIdx.x;
    if (i >= n4) return;
    float4 v = s[i];
    d[2 * i]     = __floats2half2_rn(v.x, v.y);
    d[2 * i + 1] = __floats2half2_rn(v.z, v.w);
}

// ---------------- im2col -> f16 ----------------
__global__ void im2col_kernel(const float* __restrict__ x, __half* __restrict__ out) {
    int idx = blockIdx.x * 256 + threadIdx.x;
    if (idx >= NTOK * DMODEL) return;
    int t = idx / 768, r = idx % 768;
    int c = r >> 8;
    int ij = r & 255;
    int i = ij >> 4, j = ij & 15;
    int b = t / 196, p = t % 196;
    int py = p / 14, px = p % 14;
    out[idx] = __float2half_rn(x[((size_t)(b * 3 + c) * 224 + py * 16 + i) * 224 + px * 16 + j]);
}

// ---------------- fp16 mma GEMM: C[M,N] = A[M,K] @ W[N,K]^T (+epilogue) ----------------
// 128x128x64 tile, 256 threads (8 warps 2x4), warp tile 64x32.
// 3-stage cp.async ring (BK=64), ONE __syncthreads per chunk, ldmatrix, 2 CTAs/SM.
#define TPADH  72                      // halves; 144B rows; ldmatrix rows stride 36 banks (conflict-free)
#define TILEH  (128 * TPADH)
#define STAGEH (2 * TILEH)
#define GSMEM  (3 * STAGEH * 2)        // 110592 bytes

__device__ __forceinline__ void load_tile_pair(unsigned sdst, const __half* __restrict__ Ab,
                                               const __half* __restrict__ Wb, int K, int k0, int tid)
{
#pragma unroll
    for (int half_ = 0; half_ < 2; half_++) {
        const __half* src = (half_ ? Wb : Ab) + k0;
        unsigned base = sdst + half_ * (TILEH * 2);
#pragma unroll
        for (int j = 0; j < 4; j++) {
            int i = (j << 8) + tid;            // 0..1023 16B segments
            int row = i >> 3, c16 = i & 7;
            unsigned d = base + (row * TPADH + (c16 << 3)) * 2;
            const __half* s = src + (size_t)row * K + (c16 << 3);
            asm volatile("cp.async.cg.shared.global [%0], [%1], 16;" :: "r"(d), "l"(s));
        }
    }
}

__global__ void __launch_bounds__(256, 2) gemm_mma(
    const __half* __restrict__ A, const __half* __restrict__ W,
    const float* __restrict__ bias, const float* __restrict__ res,
    const float* __restrict__ pos, float* __restrict__ Cf,
    __half* __restrict__ Ch, int N, int K, int act)
{
    extern __shared__ __half smh[];
    const int tid = threadIdx.x;
    const int bm = blockIdx.y << 7, bn = blockIdx.x << 7;
    const int wid = tid >> 5, lane = tid & 31;
    const int wm = wid >> 2, wn = wid & 3;
    const int lr = lane >> 2, lc = lane & 3;
    unsigned sbase;
    asm("{ .reg .u64 t; cvta.to.shared.u64 t, %1; cvt.u32.u64 %0, t; }" : "=r"(sbase) : "l"(smh));

    const __half* Ab = A + (size_t)bm * K;
    const __half* Wb = W + (size_t)bn * K;
    const int NC = K >> 6;             // BK=64 chunks

    // ldmatrix per-lane base offsets (bytes within a stage)
    unsigned a_off[4];
#pragma unroll
    for (int mi = 0; mi < 4; mi++) {
        int row = wm * 64 + mi * 16 + (lane & 7) + (((lane >> 3) & 1) << 3);
        a_off[mi] = sbase + ((unsigned)(row * TPADH + ((lane >> 4) << 3)) << 1);
    }
    unsigned b_off[2];
#pragma unroll
    for (int nj = 0; nj < 2; nj++) {
        int row = wn * 32 + nj * 16 + ((lane >> 4) << 3) + (lane & 7);
        b_off[nj] = sbase + TILEH * 2 +
                    ((unsigned)(row * TPADH + (((lane >> 3) & 1) << 3)) << 1);
    }

    float acc[4][4][4];
#pragma unroll
    for (int mi = 0; mi < 4; mi++)
#pragma unroll
        for (int ni = 0; ni < 4; ni++)
#pragma unroll
            for (int q = 0; q < 4; q++) acc[mi][ni][q] = 0.f;

    // prologue: stages 0,1
    load_tile_pair(sbase,              Ab, Wb, K, 0,  tid);
    asm volatile("cp.async.commit_group;" ::: "memory");
    load_tile_pair(sbase + STAGEH * 2, Ab, Wb, K, 64, tid);
    asm volatile("cp.async.commit_group;" ::: "memory");

    for (int c = 0; c < NC; c++) {
        asm volatile("cp.async.wait_group 1;" ::: "memory");   // chunk c resident
        __syncthreads();   // everyone done reading slot (c+2)%3's old contents

        if (c + 2 < NC)
            load_tile_pair(sbase + ((c + 2) % 3) * (STAGEH * 2), Ab, Wb, K, (c + 2) << 6, tid);
        asm volatile("cp.async.commit_group;" ::: "memory");

        const unsigned soff = (unsigned)((c % 3) * (STAGEH * 2));
#pragma unroll
        for (int kk = 0; kk < 4; kk++) {
            const unsigned koff = soff + (kk << 5);            // kk*16 halves = 32B
            unsigned af[4][4], bf[4][2];
#pragma unroll
            for (int mi = 0; mi < 4; mi++)
                ldm_x4(af[mi][0], af[mi][1], af[mi][2], af[mi][3], a_off[mi] + koff);
#pragma unroll
            for (int nj = 0; nj < 2; nj++)
                ldm_x4(bf[2 * nj][0], bf[2 * nj][1], bf[2 * nj + 1][0], bf[2 * nj + 1][1],
                       b_off[nj] + koff);
#pragma unroll
            for (int mi = 0; mi < 4; mi++)
#pragma unroll
                for (int ni = 0; ni < 4; ni++)
                    mma_f16(acc[mi][ni], af[mi], bf[ni]);
        }
    }

    // ---- epilogue: fp32 math, output fp32 (Cf) or fp16 (Ch) ----
#pragma unroll
    for (int mi = 0; mi < 4; mi++) {
#pragma unroll
        for (int half_ = 0; half_ < 2; half_++) {
            const int m = bm + wm * 64 + mi * 16 + lr + half_ * 8;
            const float* rrow = res ? res + (size_t)m * N : nullptr;
            const float* prow = pos ? pos + (size_t)(m % NSEQ) * N : nullptr;
#pragma unroll
            for (int ni = 0; ni < 4; ni++) {
                const int n = bn + wn * 32 + ni * 8 + 2 * lc;
                float v0 = acc[mi][ni][half_ * 2 + 0];
                float v1 = acc[mi][ni][half_ * 2 + 1];
                v0 += bias[n]; v1 += bias[n + 1];
                if (act) {
                    v0 = 0.5f * v0 * (1.f + erff(v0 * 0.70710678118654752f));
                    v1 = 0.5f * v1 * (1.f + erff(v1 * 0.70710678118654752f));
                }
                if (prow) { v0 += prow[n]; v1 += prow[n + 1]; }
                if (rrow) { v0 += rrow[n]; v1 += rrow[n + 1]; }
                if (Ch) {
                    *(__half2*)(Ch + (size_t)m * N + n) = __floats2half2_rn(v0, v1);
                } else {
                    *(float2*)(Cf + (size_t)m * N + n) = make_float2(v0, v1);
                }
            }
        }
    }
}

// ---------------- LayerNorm: fp32 in, fp16 or fp32 out ----------------
__global__ void __launch_bounds__(256) ln_kernel(
    const float* __restrict__ X, const float* __restrict__ w,
    const float* __restrict__ b, float* __restrict__ Yf, __half* __restrict__ Yh)
{
    const int t = blockIdx.x;
    const int tid = threadIdx.x;
    const float* xr = X + (size_t)t * DMODEL;
    float v0 = xr[tid], v1 = xr[tid + 256], v2 = xr[tid + 512];
    float s = v0 + v1 + v2;
    float s2 = v0 * v0 + v1 * v1 + v2 * v2;
#pragma unroll
    for (int o = 16; o > 0; o >>= 1) {
        s += __shfl_xor_sync(0xffffffffu, s, o);
        s2 += __shfl_xor_sync(0xffffffffu, s2, o);
    }
    __shared__ float rs[8], rs2[8];
    __shared__ float mS, rS;
    int wid = tid >> 5, lane = tid & 31;
    if (lane == 0) { rs[wid] = s; rs2[wid] = s2; }
    __syncthreads();
    if (tid == 0) {
        float S = 0.f, S2 = 0.f;
        for (int k = 0; k < 8; k++) { S += rs[k]; S2 += rs2[k]; }
        float m = S * (1.f / 768.f);
        float var = S2 * (1.f / 768.f) - m * m;
        mS = m;
        rS = rsqrtf(var + 1e-5f);
    }
    __syncthreads();
    float m = mS, r = rS;
    float o0 = (v0 - m) * r * w[tid] + b[tid];
    float o1 = (v1 - m) * r * w[tid + 256] + b[tid + 256];
    float o2 = (v2 - m) * r * w[tid + 512] + b[tid + 512];
    if (Yh) {
        __half* yr = Yh + (size_t)t * DMODEL;
        yr[tid] = __float2half_rn(o0);
        yr[tid + 256] = __float2half_rn(o1);
        yr[tid + 512] = __float2half_rn(o2);
    } else {
        float* yr = Yf + (size_t)t * DMODEL;
        yr[tid] = o0; yr[tid + 256] = o1; yr[tid + 512] = o2;
    }
}

// ---------------- fused attention, fp16 mma (m16n8k16) ----------------
#define KP    224
#define KSTRH 72     // halves
#define VSTRH 232    // halves
#define SSTRF 228    // floats
#define AT_KS   0
#define AT_VT   (AT_KS + KP * KSTRH * 2)
#define AT_QS   (AT_VT + 64 * VSTRH * 2)
#define AT_SSF  (AT_QS + 64 * KSTRH * 2)
#define AT_PS   (AT_SSF + 64 * SSTRF * 4)
#define ATTN_SMEM_BYTES (AT_PS + 64 * VSTRH * 2)   // 159232

__global__ void __launch_bounds__(256) attn_kernel(
    const __half* __restrict__ qkv, __half* __restrict__ O)
{
    extern __shared__ char smc[];
    __half* Ks  = (__half*)(smc + AT_KS);
    __half* Vt  = (__half*)(smc + AT_VT);
    __half* Qs  = (__half*)(smc + AT_QS);
    float*  Ssf = (float* )(smc + AT_SSF);
    __half* Ps  = (__half*)(smc + AT_PS);

    const int tid = threadIdx.x;
    const int b = blockIdx.x / NHEAD;
    const int h = blockIdx.x % NHEAD;
    const size_t base = (size_t)b * NSEQ * QKVDIM + h * 64;

    for (int idx = tid; idx < KP * 64; idx += 256) {
        int m = idx >> 6, d = idx & 63;
        __half kv = __float2half_rn(0.f), vv = kv;
        if (m < NSEQ) {
            kv = qkv[base + (size_t)m * QKVDIM + 768 + d];
            vv = qkv[base + (size_t)m * QKVDIM + 1536 + d];
        }
        Ks[m * KSTRH + d] = kv;
        Vt[d * VSTRH + m] = vv;
    }
    __syncthreads();

    const int wid = tid >> 5, lane = tid & 31;
    const int lr = lane >> 2, lc = lane & 3;
    const int wm = wid >> 2, wn = wid & 3;

    for (int q0 = 0; q0 < NSEQ; q0 += 64) {
        for (int idx = tid; idx < 64 * 64; idx += 256) {
            int i = idx >> 6, d = idx & 63;
            int r = q0 + i; if (r > NSEQ - 1) r = NSEQ - 1;
            Qs[i * KSTRH + d] = __float2half_rn(__half2float(qkv[base + (size_t)r * QKVDIM + d]) * 0.125f);
        }
        __syncthreads();

        // ---- S[64][224] = Q @ K^T : warp tile 32x56, K=64 ----
        {
            float acc[2][7][4];
#pragma unroll
            for (int mi = 0; mi < 2; mi++)
#pragma unroll
                for (int ni = 0; ni < 7; ni++)
#pragma unroll
                    for (int q = 0; q < 4; q++) acc[mi][ni][q] = 0.f;
#pragma unroll
            for (int kk = 0; kk < 4; kk++) {
                const int koff = (kk << 4) + (lc << 1);
                unsigned af[2][4], bf[7][2];
#pragma unroll
                for (int mi = 0; mi < 2; mi++) {
                    const __half* ap = Qs + (wm * 32 + mi * 16 + lr) * KSTRH + koff;
                    af[mi][0] = *(const unsigned*)(ap);
                    af[mi][1] = *(const unsigned*)(ap + 8 * KSTRH);
                    af[mi][2] = *(const unsigned*)(ap + 8);
                    af[mi][3] = *(const unsigned*)(ap + 8 * KSTRH + 8);
                }
#pragma unroll
                for (int ni = 0; ni < 7; ni++) {
                    const __half* bp = Ks + (wn * 56 + ni * 8 + lr) * KSTRH + koff;
                    bf[ni][0] = *(const unsigned*)(bp);
                    bf[ni][1] = *(const unsigned*)(bp + 8);
                }
#pragma unroll
                for (int mi = 0; mi < 2; mi++)
#pragma unroll
                    for (int ni = 0; ni < 7; ni++)
                        mma_f16(acc[mi][ni], af[mi], bf[ni]);
            }
#pragma unroll
            for (int mi = 0; mi < 2; mi++) {
                const int r0 = wm * 32 + mi * 16 + lr;
#pragma unroll
                for (int ni = 0; ni < 7; ni++) {
                    const int c0 = wn * 56 + ni * 8 + 2 * lc;
                    Ssf[r0 * SSTRF + c0]           = acc[mi][ni][0];
                    Ssf[r0 * SSTRF + c0 + 1]       = acc[mi][ni][1];
                    Ssf[(r0 + 8) * SSTRF + c0]     = acc[mi][ni][2];
                    Ssf[(r0 + 8) * SSTRF + c0 + 1] = acc[mi][ni][3];
                }
            }
        }
        __syncthreads();

        // ---- softmax (fp32) -> Ps (fp16), zero pads ----
        for (int row = wid; row < 64; row += 8) {
            const float* srow = Ssf + row * SSTRF;
            __half* prow = Ps + row * VSTRH;
            float mx = -1e30f;
            for (int m = lane; m < NSEQ; m += 32) mx = fmaxf(mx, srow[m]);
#pragma unroll
            for (int o = 16; o > 0; o >>= 1) mx = fmaxf(mx, __shfl_xor_sync(0xffffffffu, mx, o));
            float sum = 0.f;
            float ebuf[7];
            for (int m = lane, q = 0; m < NSEQ; m += 32, q++) {
                float e = expf(srow[m] - mx);
                ebuf[q] = e;
                sum += e;
            }
#pragma unroll
            for (int o = 16; o > 0; o >>= 1) sum += __shfl_xor_sync(0xffffffffu, sum, o);
            float inv = 1.f / sum;
            for (int m = lane, q = 0; m < NSEQ; m += 32, q++)
                prow[m] = __float2half_rn(ebuf[q] * inv);
            if (lane < KP - NSEQ) prow[NSEQ + lane] = __float2half_rn(0.f);
        }
        __syncthreads();

        // ---- O[64][64] = P @ V : warp tile 32x16, K=224 ----
        {
            float acc2[2][2][4];
#pragma unroll
            for (int mi = 0; mi < 2; mi++)
#pragma unroll
                for (int ni = 0; ni < 2; ni++)
#pragma unroll
                    for (int q = 0; q < 4; q++) acc2[mi][ni][q] = 0.f;
#pragma unroll
            for (int kk = 0; kk < 14; kk++) {
                const int koff = (kk << 4) + (lc << 1);
                unsigned af[2][4], bf[2][2];
#pragma unroll
                for (int mi = 0; mi < 2; mi++) {
                    const __half* ap = Ps + (wm * 32 + mi * 16 + lr) * VSTRH + koff;
                    af[mi][0] = *(const unsigned*)(ap);
                    af[mi][1] = *(const unsigned*)(ap + 8 * VSTRH);
                    af[mi][2] = *(const unsigned*)(ap + 8);
                    af[mi][3] = *(const unsigned*)(ap + 8 * VSTRH + 8);
                }
#pragma unroll
                for (int ni = 0; ni < 2; ni++) {
                    const __half* bp = Vt + (wn * 16 + ni * 8 + lr) * VSTRH + koff;
                    bf[ni][0] = *(const unsigned*)(bp);
                    bf[ni][1] = *(const unsigned*)(bp + 8);
                }
#pragma unroll
                for (int mi = 0; mi < 2; mi++)
#pragma unroll
                    for (int ni = 0; ni < 2; ni++)
                        mma_f16(acc2[mi][ni], af[mi], bf[ni]);
            }
#pragma unroll
            for (int mi = 0; mi < 2; mi++) {
#pragma unroll
                for (int half_ = 0; half_ < 2; half_++) {
                    const int r = q0 + wm * 32 + mi * 16 + lr + half_ * 8;
                    if (r < NSEQ) {
                        __half* orow = O + (size_t)(b * NSEQ + r) * DMODEL + h * 64;
#pragma unroll
                        for (int ni = 0; ni < 2; ni++) {
                            const int n = wn * 16 + ni * 8 + 2 * lc;
                            *(__half2*)(orow + n) =
                                __floats2half2_rn(acc2[mi][ni][half_ * 2 + 0], acc2[mi][ni][half_ * 2 + 1]);
                        }
                    }
                }
            }
        }
        __syncthreads();
    }
}

// ---------------- launch ----------------
extern "C" void kernel_launch(void* const* d_in, const int* in_sizes, int n_in,
                              void* d_out, int out_size)
{
    const float* x       = (const float*)d_in[0];
    const float* patch_w = (const float*)d_in[1];
    const float* patch_b = (const float*)d_in[2];
    const float* pos     = (const float*)d_in[3];
    const float* ln1_w   = (const float*)d_in[4];
    const float* ln1_b   = (const float*)d_in[5];
    const float* qkv_w   = (const float*)d_in[6];
    const float* qkv_b   = (const float*)d_in[7];
    const float* proj_w  = (const float*)d_in[8];
    const float* proj_b  = (const float*)d_in[9];
    const float* ln2_w   = (const float*)d_in[10];
    const float* ln2_b   = (const float*)d_in[11];
    const float* fc1_w   = (const float*)d_in[12];
    const float* fc1_b   = (const float*)d_in[13];
    const float* fc2_w   = (const float*)d_in[14];
    const float* fc2_b   = (const float*)d_in[15];
    const float* lnf_w   = (const float*)d_in[16];
    const float* lnf_b   = (const float*)d_in[17];

    float *h; __half *y, *qkv, *o, *ff, *im, *w;
    cudaGetSymbolAddress((void**)&h,   g_h);
    cudaGetSymbolAddress((void**)&y,   g_y);
    cudaGetSymbolAddress((void**)&qkv, g_qkv);
    cudaGetSymbolAddress((void**)&o,   g_o);
    cudaGetSymbolAddress((void**)&ff,  g_ff);
    cudaGetSymbolAddress((void**)&im,  g_im);
    cudaGetSymbolAddress((void**)&w,   g_w);

    cudaFuncSetAttribute(attn_kernel, cudaFuncAttributeMaxDynamicSharedMemorySize, ATTN_SMEM_BYTES);
    cudaFuncSetAttribute(gemm_mma, cudaFuncAttributeMaxDynamicSharedMemorySize, GSMEM);

    // order: profiled launch index 3 = patch-embed gemm_mma
    cvt_kernel<<<(  589824/4 + 255)/256, 256>>>((const float4*)patch_w,(__half2*)(w + OPATCH),   589824/4); // 0
    im2col_kernel<<<(NTOK * DMODEL + 255) / 256, 256>>>(x, im);                                             // 1
    cvt_kernel<<<(21233664/4 + 255)/256, 256>>>((const float4*)qkv_w,  (__half2*)(w + OQKV),   21233664/4); // 2
    gemm_mma<<<dim3(DMODEL / 128, NTOK / 128), 256, GSMEM>>>(                                               // 3 <- profiled
        im, w + OPATCH, patch_b, nullptr, pos, h, nullptr, DMODEL, DMODEL, 0);
    cvt_kernel<<<( 7077888/4 + 255)/256, 256>>>((const float4*)proj_w, (__half2*)(w + OPROJ),   7077888/4); // 4
    cvt_kernel<<<(28311552/4 + 255)/256, 256>>>((const float4*)fc1_w,  (__half2*)(w + OFC1),   28311552/4); // 5
    cvt_kernel<<<(28311552/4 + 255)/256, 256>>>((const float4*)fc2_w,  (__half2*)(w + OFC2),   28311552/4); // 6

    for (int l = 0; l < NLAYER; l++) {
        ln_kernel<<<NTOK, 256>>>(h, ln1_w + l * DMODEL, ln1_b + l * DMODEL, nullptr, y);
        gemm_mma<<<dim3(QKVDIM / 128, NTOK / 128), 256, GSMEM>>>(
            y, w + OQKV + (size_t)l * QKVDIM * DMODEL, qkv_b + l * QKVDIM,
            nullptr, nullptr, nullptr, qkv, QKVDIM, DMODEL, 0);
        attn_kernel<<<32 * NHEAD, 256, ATTN_SMEM_BYTES>>>(qkv, o);
        gemm_mma<<<dim3(DMODEL / 128, NTOK / 128), 256, GSMEM>>>(
            o, w + OPROJ + (size_t)l * DMODEL * DMODEL, proj_b + l * DMODEL,
            h, nullptr, h, nullptr, DMODEL, DMODEL, 0);
        ln_kernel<<<NTOK, 256>>>(h, ln2_w + l * DMODEL, ln2_b + l * DMODEL, nullptr, y);
        gemm_mma<<<dim3(FFDIM / 128, NTOK / 128), 256, GSMEM>>>(
            y, w + OFC1 + (size_t)l * FFDIM * DMODEL, fc1_b + l * FFDIM,
            nullptr, nullptr, nullptr, ff, FFDIM, DMODEL, 1);
        gemm_mma<<<dim3(DMODEL / 128, NTOK / 128), 256, GSMEM>>>(
            ff, w + OFC2 + (size_t)l * DMODEL * FFDIM, fc2_b + l * DMODEL,
            h, nullptr, h, nullptr, DMODEL, FFDIM, 0);
    }
    ln_kernel<<<NTOK, 256>>>(h, lnf_w, lnf_b, (float*)d_out, nullptr);
}